// round 12
// baseline (speedup 1.0000x reference)
#include <cuda_runtime.h>
#include <cuda_fp16.h>
#include <cstdint>

// ===== problem constants =====
#define RTOT  32768
#define CDIM  256
#define KTOT  8192
#define MT    128
#define NT    64               // 32KB B stages
#define KSTEPS 16
#define NUM_MT (RTOT/MT)       // 256
#define NUM_NT (KTOT/NT)       // 128
#define JOBS  (NUM_MT*NUM_NT)  // 32768
#define NCTA  148
#define THREADS 256

#define SMEM_A    0
#define SMEM_B    65536        // 4 stages x 32KB
#define SMEM_BAR  196608
#define SMEM_TOTAL 196736

#define IDX_OFF  8388608
#define DIST_OFF (8388608+32768)

#define VOFF 1024.0f
#define MARGIN 0.09f
#define FIXROWS 16
#define KSLICES 8

// ===== device globals (static scratch) =====
__device__ uint4 g_Aimg[(size_t)NUM_MT*4096];
__device__ uint4 g_Bimg[(size_t)NUM_NT*2048];
__device__ float g_cbsq[KTOT];
__device__ float g_cbsqo[KTOT];
__device__ float g_xsq[RTOT];
__device__ int   g_idx[RTOT];
__device__ unsigned long long g_best[RTOT];
__device__ unsigned int g_best2[RTOT];
__device__ int g_fixcnt;
__device__ int g_fixrows[RTOT];
__device__ int g_isfix[RTOT];
__device__ unsigned long long g_fbest[RTOT];

// ===== helpers =====
__device__ __forceinline__ uint32_t smem_u32(const void* p) {
    uint32_t a;
    asm("{ .reg .u64 t; cvta.to.shared.u64 t, %1; cvt.u32.u64 %0, t; }" : "=r"(a) : "l"(p));
    return a;
}
__device__ __forceinline__ void cp_async16(uint32_t sa, const void* g) {
    asm volatile("cp.async.cg.shared.global [%0], [%1], 16;" :: "r"(sa), "l"(g));
}
#define CP_COMMIT() asm volatile("cp.async.commit_group;" ::: "memory")
#define CP_WAIT(N)  asm volatile("cp.async.wait_group %0;" :: "n"(N) : "memory")

#define MBARRIER_INIT(mb, c) asm volatile("mbarrier.init.shared.b64 [%0], %1;" :: "r"((uint32_t)(mb)), "r"((uint32_t)(c)) : "memory")
#define MBARRIER_ARRIVE(mb)  asm volatile("mbarrier.arrive.shared.b64 _, [%0];" :: "r"((uint32_t)(mb)) : "memory")
#define CP_ASYNC_MBAR_ARRIVE(mb) asm volatile("cp.async.mbarrier.arrive.noinc.shared.b64 [%0];" :: "r"((uint32_t)(mb)) : "memory")

#define MBAR_WAIT(mb, par) do {                                                   \
    uint32_t _m = (uint32_t)(mb), _p = (uint32_t)(par), _d;                       \
    asm volatile("{\n\t.reg .pred p;\n\t"                                         \
        "mbarrier.try_wait.parity.acquire.cta.shared::cta.b64 p, [%1], %2;\n\t"   \
        "selp.b32 %0,1,0,p;\n\t}" : "=r"(_d) : "r"(_m), "r"(_p) : "memory");      \
    if (!_d) {                                                                    \
        asm volatile("{\n\t.reg .pred P1;\n\t"                                    \
        "WL_%=:\n\t"                                                              \
        "mbarrier.try_wait.parity.acquire.cta.shared::cta.b64 P1, [%0], %1, 0x989680;\n\t" \
        "@P1 bra.uni WD_%=;\n\t"                                                  \
        "bra.uni WL_%=;\n\t"                                                      \
        "WD_%=:\n\t}" :: "r"(_m), "r"(_p) : "memory");                            \
    }                                                                             \
} while (0)

__device__ __forceinline__ void ldsm4(uint32_t* r, uint32_t addr) {
    asm volatile("ldmatrix.sync.aligned.m8n8.x4.shared.b16 {%0,%1,%2,%3}, [%4];"
        : "=r"(r[0]), "=r"(r[1]), "=r"(r[2]), "=r"(r[3]) : "r"(addr));
}
__device__ __forceinline__ void mma16816(float* c, const uint32_t* a, uint32_t b0, uint32_t b1) {
    asm volatile("mma.sync.aligned.m16n8k16.row.col.f32.f16.f16.f32 "
        "{%0,%1,%2,%3}, {%4,%5,%6,%7}, {%8,%9}, {%0,%1,%2,%3};"
        : "+f"(c[0]), "+f"(c[1]), "+f"(c[2]), "+f"(c[3])
        : "r"(a[0]), "r"(a[1]), "r"(a[2]), "r"(a[3]), "r"(b0), "r"(b1));
}
__device__ __forceinline__ uint32_t encf(float f) {
    uint32_t u = __float_as_uint(f);
    return (u & 0x80000000u) ? ~u : (u | 0x80000000u);
}
__device__ __forceinline__ float decf(uint32_t e) {
    uint32_t u = (e & 0x80000000u) ? (e & 0x7fffffffu) : ~e;
    return __uint_as_float(u);
}
__device__ __forceinline__ uint32_t packh2(__half a, __half b) {
    __half2 h = __halves2half2(a, b);
    return *reinterpret_cast<uint32_t*>(&h);
}

// ===== launch #1: init =====
__global__ void init_kernel() {
    int i = blockIdx.x * 256 + threadIdx.x;
    g_best[i] = ~0ull;
    g_best2[i] = 0xFFFFFFFFu;
    g_isfix[i] = 0;
    g_fbest[i] = ~0ull;
    if (i == 0) g_fixcnt = 0;
}

// ===== launches #2/#3: prep =====
__global__ void prep_a_kernel(const float* __restrict__ x) {
    int t = blockIdx.x * 256 + threadIdx.x;
    int row = t >> 5, u = t & 31;
    int ks = u >> 1, kh = u & 1;
    const float* r = x + (size_t)row * CDIM + ks * 16 + kh * 8;
    float s = 0.f;
    __half h[8];
#pragma unroll
    for (int i = 0; i < 8; ++i) { float v = r[i]; s = fmaf(v, v, s); h[i] = __float2half(v); }
    uint4 val;
    val.x = packh2(h[0], h[1]); val.y = packh2(h[2], h[3]);
    val.z = packh2(h[4], h[5]); val.w = packh2(h[6], h[7]);
    int tile = row >> 7, rl = row & 127;
    int phys = (rl * 2 + kh) ^ ((rl >> 2) & 1);
    g_Aimg[(size_t)tile * 4096 + ks * 256 + phys] = val;
#pragma unroll
    for (int o = 16; o; o >>= 1) s += __shfl_xor_sync(0xffffffffu, s, o);
    if ((t & 31) == 0) g_xsq[row] = s;
}
__global__ void prep_b_kernel(const float* __restrict__ cb) {
    int t = blockIdx.x * 256 + threadIdx.x;
    int row = t >> 5, u = t & 31;
    int ks = u >> 1, kh = u & 1;
    const float* r = cb + (size_t)row * CDIM + ks * 16 + kh * 8;
    float s = 0.f;
    __half h[8];
#pragma unroll
    for (int i = 0; i < 8; ++i) { float v = r[i]; s = fmaf(v, v, s); h[i] = __float2half(v); }
    uint4 val;
    val.x = packh2(h[0], h[1]); val.y = packh2(h[2], h[3]);
    val.z = packh2(h[4], h[5]); val.w = packh2(h[6], h[7]);
    int nt = row >> 6, rl = row & 63;
    int phys = (rl * 2 + kh) ^ ((rl >> 2) & 1);
    g_Bimg[(size_t)nt * 2048 + ks * 128 + phys] = val;
#pragma unroll
    for (int o = 16; o; o >>= 1) s += __shfl_xor_sync(0xffffffffu, s, o);
    if ((t & 31) == 0) { g_cbsq[row] = s; g_cbsqo[row] = s + VOFF; }
}

// ===== launch #4: main HMMA kernel, pipelined B + software-pipelined epilogue =====
__device__ __forceinline__ void issue_A(uint32_t smemA, int m, int tid) {
    const uint4* src = g_Aimg + (size_t)m * 4096 + tid;
#pragma unroll
    for (int i = 0; i < 16; ++i)
        cp_async16(smemA + (tid + i * 256) * 16, src + i * 256);
}
__device__ __forceinline__ void produce_stage(uint32_t smB, uint32_t bar, int jpi, int j, int tid) {
    int sp = jpi & 3;
    int par = (((jpi >> 2) & 1) ^ 1);
    MBAR_WAIT(bar + 32 + sp * 8, par);             // empty[sp]
    const uint4* src = g_Bimg + (size_t)(j & (NUM_NT - 1)) * 2048 + tid;
    uint32_t dst = smB + sp * 32768 + tid * 16;
#pragma unroll
    for (int i = 0; i < 8; ++i)
        cp_async16(dst + i * 4096, src + i * 256);
    CP_ASYNC_MBAR_ARRIVE(bar + sp * 8);            // full[sp]
}

// one epilogue chunk (2 candidates) of a pending job; ks selects (mt,h,pair)
#define EPI_CHUNK(PACC, PQV, PQB, ks) do {                                          \
    const int mt_ = (ks) >> 3, h_ = ((ks) >> 2) & 1, p_ = (ks) & 3;                 \
    if (p_ == 0) { ek1 = 0xFFFFFFFFu; ek2 = 0xFFFFFFFFu; }                          \
    float v0_ = fmaf(-2.f, PACC[mt_][p_][h_ * 2 + 0], PQV[p_ * 2 + 0]);             \
    float v1_ = fmaf(-2.f, PACC[mt_][p_][h_ * 2 + 1], PQV[p_ * 2 + 1]);             \
    uint32_t kk0 = (__float_as_uint(v0_) & 0xFFFFFFF8u) | (uint32_t)(p_ * 2 + 0);   \
    uint32_t kk1 = (__float_as_uint(v1_) & 0xFFFFFFF8u) | (uint32_t)(p_ * 2 + 1);   \
    uint32_t t0_ = max(ek1, kk0); ek1 = min(ek1, kk0); ek2 = min(ek2, t0_);         \
    uint32_t t1_ = max(ek1, kk1); ek1 = min(ek1, kk1); ek2 = min(ek2, t1_);         \
    if (p_ == 3) {                                                                   \
        float v1f = __uint_as_float(ek1 & 0xFFFFFFF8u);                              \
        float v2f = __uint_as_float(ek2 & 0xFFFFFFF8u);                              \
        int li_ = (int)(ek1 & 7u);                                                   \
        int gi_ = (PQB) + (li_ >> 1) * 8 + (li_ & 1);                                \
        if (v1f < rb[mt_][h_]) {                                                     \
            rs[mt_][h_] = fminf(rb[mt_][h_], v2f);                                   \
            rb[mt_][h_] = v1f; ri[mt_][h_] = gi_;                                    \
        } else {                                                                     \
            rs[mt_][h_] = fminf(rs[mt_][h_], v1f);                                   \
        }                                                                            \
    }                                                                                \
} while (0)

#define FLUSH() do {                                                                \
    _Pragma("unroll")                                                               \
    for (int mt = 0; mt < 2; ++mt)                                                  \
        _Pragma("unroll")                                                           \
        for (int h = 0; h < 2; ++h) {                                               \
            float bv = rb[mt][h], sv = rs[mt][h];                                   \
            int bi = ri[mt][h];                                                     \
            _Pragma("unroll")                                                       \
            for (int o = 1; o < 4; o <<= 1) {                                       \
                float ov = __shfl_xor_sync(0xffffffffu, bv, o);                     \
                int   oi = __shfl_xor_sync(0xffffffffu, bi, o);                     \
                float os = __shfl_xor_sync(0xffffffffu, sv, o);                     \
                if (ov < bv || (ov == bv && oi < bi)) {                             \
                    sv = fminf(bv, os); bv = ov; bi = oi;                           \
                } else {                                                            \
                    sv = fminf(sv, ov);                                             \
                }                                                                   \
            }                                                                       \
            if ((l & 3) == 0) {                                                     \
                int r = cur_m * MT + wm * 32 + mt * 16 + h * 8 + (l >> 2);          \
                unsigned long long key =                                            \
                    ((unsigned long long)encf(bv) << 32) | (uint32_t)bi;            \
                unsigned long long old = atomicMin(&g_best[r], key);                \
                uint32_t oldenc = (uint32_t)(old >> 32);                            \
                uint32_t be = encf(bv);                                             \
                uint32_t cand = min(encf(sv), max(be, oldenc));                     \
                atomicMin(&g_best2[r], cand);                                       \
            }                                                                       \
            rb[mt][h] = 3.4e38f; rs[mt][h] = 3.4e38f; ri[mt][h] = 0;                \
        }                                                                           \
} while (0)

#define JOB_BODY(ACC, QV, QB, PACC, PQV, PQB) do {                                  \
    int j_ = start + ji;                                                            \
    int ntj_ = j_ & (NUM_NT - 1);                                                   \
    int s_ = ji & 3;                                                                \
    MBAR_WAIT(bar + s_ * 8, (ji >> 2) & 1);                                         \
    QB = ntj_ * NT + wn * 32 + (l & 3) * 2;                                         \
    _Pragma("unroll")                                                               \
    for (int nb = 0; nb < 4; ++nb) {                                                \
        QV[nb * 2]     = __ldg(&g_cbsqo[QB + nb * 8]);                              \
        QV[nb * 2 + 1] = __ldg(&g_cbsqo[QB + nb * 8 + 1]);                          \
    }                                                                               \
    _Pragma("unroll")                                                               \
    for (int mt = 0; mt < 2; ++mt)                                                  \
        _Pragma("unroll")                                                           \
        for (int nb = 0; nb < 4; ++nb)                                              \
            _Pragma("unroll")                                                       \
            for (int q = 0; q < 4; ++q) ACC[mt][nb][q] = 0.f;                       \
    uint32_t Bstage_ = smB + s_ * 32768;                                            \
    _Pragma("unroll")                                                               \
    for (int ks = 0; ks < KSTEPS; ++ks) {                                           \
        uint32_t Apan_ = smA + ks * 4096;                                           \
        uint32_t Bpan_ = Bstage_ + ks * 2048;                                       \
        uint32_t af_[2][4], bf_[2][4];                                              \
        ldsm4(af_[0], Apan_ + aoff[0]);                                             \
        ldsm4(af_[1], Apan_ + aoff[1]);                                             \
        ldsm4(bf_[0], Bpan_ + boff[0]);                                             \
        ldsm4(bf_[1], Bpan_ + boff[1]);                                             \
        _Pragma("unroll")                                                           \
        for (int mt = 0; mt < 2; ++mt)                                              \
            _Pragma("unroll")                                                       \
            for (int g = 0; g < 2; ++g) {                                           \
                mma16816(ACC[mt][g*2  ], af_[mt], bf_[g][0], bf_[g][1]);            \
                mma16816(ACC[mt][g*2+1], af_[mt], bf_[g][2], bf_[g][3]);            \
            }                                                                       \
        if (hp) EPI_CHUNK(PACC, PQV, PQB, ks);   /* hidden under MMA shadow */      \
    }                                                                               \
    MBARRIER_ARRIVE(bar + 32 + s_ * 8);                                             \
    if (ji + 3 < njobs) produce_stage(smB, bar, ji + 3, start + ji + 3, tid);       \
    if (ntj_ == NUM_NT - 1 || ji == njobs - 1) {                                    \
        _Pragma("unroll")                                                           \
        for (int ks = 0; ks < KSTEPS; ++ks) EPI_CHUNK(ACC, QV, QB, ks);             \
        FLUSH();                                                                    \
        hp = false;                                                                 \
        int jn_ = j_ + 1;                                                           \
        if (jn_ < end) {                                                            \
            int nm_ = jn_ >> 7;                                                     \
            if (nm_ != cur_m) {                                                     \
                cur_m = nm_;                                                        \
                __syncthreads();                                                    \
                issue_A(smA, cur_m, tid); CP_COMMIT();                              \
                CP_WAIT(0);                                                         \
                __syncthreads();                                                    \
            }                                                                       \
        }                                                                           \
    } else {                                                                        \
        hp = true;                                                                  \
    }                                                                               \
    ++ji;                                                                           \
} while (0)

__global__ __launch_bounds__(THREADS, 1)
void vq_hmma_kernel() {
    extern __shared__ char smem[];
    uint32_t sb = smem_u32(smem);
    uint32_t smA = sb + SMEM_A;
    uint32_t smB = sb + SMEM_B;
    uint32_t bar = sb + SMEM_BAR;

    int tid = threadIdx.x;
    int l = tid & 31, w = tid >> 5;
    int wm = w >> 1, wn = w & 1;

    uint32_t aoff[2], boff[2];
#pragma unroll
    for (int mt = 0; mt < 2; ++mt) {
        int row = wm * 32 + mt * 16 + (l & 15);
        int kh = l >> 4;
        aoff[mt] = (uint32_t)(((row * 2 + kh) ^ ((row >> 2) & 1)) << 4);
    }
#pragma unroll
    for (int g = 0; g < 2; ++g) {
        int code = wn * 32 + g * 16 + (l & 7) + ((l >> 4) << 3);
        int kh = (l >> 3) & 1;
        boff[g] = (uint32_t)(((code * 2 + kh) ^ ((code >> 2) & 1)) << 4);
    }

    int start = (int)(((long long)blockIdx.x * JOBS) / NCTA);
    int end   = (int)(((long long)(blockIdx.x + 1) * JOBS) / NCTA);
    int njobs = end - start;

    if (tid == 0) {
#pragma unroll
        for (int s = 0; s < 4; ++s) {
            MBARRIER_INIT(bar + s * 8, 256);        // full
            MBARRIER_INIT(bar + 32 + s * 8, 256);   // empty
        }
    }
    __syncthreads();

    int cur_m = start >> 7;
    issue_A(smA, cur_m, tid); CP_COMMIT();
#pragma unroll
    for (int p = 0; p < 3; ++p)
        if (p < njobs) produce_stage(smB, bar, p, start + p, tid);
    CP_WAIT(0);
    __syncthreads();

    float rb[2][2] = {{3.4e38f,3.4e38f},{3.4e38f,3.4e38f}};
    float rs[2][2] = {{3.4e38f,3.4e38f},{3.4e38f,3.4e38f}};
    int   ri[2][2] = {{0,0},{0,0}};

    float accA[2][4][4], accB[2][4][4];
    float qvA[8], qvB[8];
    int qbA = 0, qbB = 0;
    uint32_t ek1 = 0xFFFFFFFFu, ek2 = 0xFFFFFFFFu;
    bool hp = false;

    int ji = 0;
    while (ji < njobs) {
        JOB_BODY(accA, qvA, qbA, accB, qvB, qbB);
        if (ji >= njobs) break;
        JOB_BODY(accB, qvB, qbB, accA, qvA, qbA);
    }
}

// ===== launch #5: finalize, flag close rows =====
__global__ void final_kernel(float* __restrict__ out) {
    int i = blockIdx.x * 256 + threadIdx.x;
    unsigned long long key = g_best[i];
    int idx = (int)(uint32_t)key;
    float val = decf((uint32_t)(key >> 32)) - VOFF;
    float sec = decf(g_best2[i]) - VOFF;
    out[IDX_OFF + i]  = (float)idx;
    out[DIST_OFF + i] = g_xsq[i] + val;
    g_idx[i] = idx;
    if (sec - val < MARGIN) {
        g_isfix[i] = 1;
        int p = atomicAdd(&g_fixcnt, 1);
        g_fixrows[p] = i;
    }
}

// ===== launch #6: exact fp32 rescan, K-sliced 8-way =====
__global__ __launch_bounds__(256) void fixup_kernel(const float* __restrict__ x,
                                                    const float* __restrict__ cb) {
    __shared__ float4 xs[FIXROWS][64];
    __shared__ unsigned long long wk[FIXROWS][2];
    int tid = threadIdx.x;
    int n = g_fixcnt;
    int ngroups = (n + FIXROWS - 1) / FIXROWS;
    int slice = blockIdx.x & (KSLICES - 1);
    int g0 = blockIdx.x >> 3;
    const float4* c4 = reinterpret_cast<const float4*>(cb);
    for (int g = g0; g < ngroups; g += NCTA) {
        __syncthreads();
        for (int i = tid; i < FIXROWS * 64; i += 256) {
            int r = i >> 6, q = i & 63;
            int fr = g * FIXROWS + r;
            int row = g_fixrows[(fr < n) ? fr : g * FIXROWS];
            xs[r][q] = reinterpret_cast<const float4*>(x)[(size_t)row * 64 + q];
        }
        __syncthreads();
        int rg = tid >> 6;
        int cg = tid & 63;
        float bv[4] = {3.4e38f,3.4e38f,3.4e38f,3.4e38f};
        int   bi[4] = {0,0,0,0};
        for (int k = slice * 4; k < slice * 4 + 4; ++k) {
            int c0 = k * 256 + cg * 4;
            float acc[4][4];
#pragma unroll
            for (int r = 0; r < 4; ++r)
#pragma unroll
                for (int cc = 0; cc < 4; ++cc) acc[r][cc] = 0.f;
#pragma unroll 8
            for (int q = 0; q < 64; ++q) {
                float4 xv[4];
#pragma unroll
                for (int r = 0; r < 4; ++r) xv[r] = xs[rg * 4 + r][q];
#pragma unroll
                for (int cc = 0; cc < 4; ++cc) {
                    float4 v = c4[(size_t)(c0 + cc) * 64 + q];
#pragma unroll
                    for (int r = 0; r < 4; ++r) {
                        acc[r][cc] = fmaf(v.x, xv[r].x, acc[r][cc]);
                        acc[r][cc] = fmaf(v.y, xv[r].y, acc[r][cc]);
                        acc[r][cc] = fmaf(v.z, xv[r].z, acc[r][cc]);
                        acc[r][cc] = fmaf(v.w, xv[r].w, acc[r][cc]);
                    }
                }
            }
#pragma unroll
            for (int cc = 0; cc < 4; ++cc) {
                float cq = __ldg(&g_cbsq[c0 + cc]);
#pragma unroll
                for (int r = 0; r < 4; ++r) {
                    float val = fmaf(-2.f, acc[r][cc], cq);
                    if (val < bv[r] || (val == bv[r] && c0 + cc < bi[r])) {
                        bv[r] = val; bi[r] = c0 + cc;
                    }
                }
            }
        }
#pragma unroll
        for (int r = 0; r < 4; ++r) {
            unsigned long long key =
                ((unsigned long long)encf(bv[r]) << 32) | (uint32_t)bi[r];
#pragma unroll
            for (int o = 16; o; o >>= 1) {
                unsigned long long ok = __shfl_xor_sync(0xffffffffu, key, o);
                key = min(key, ok);
            }
            if ((tid & 31) == 0) wk[rg * 4 + r][(tid >> 5) & 1] = key;
        }
        __syncthreads();
        if (tid < FIXROWS) {
            int fr = g * FIXROWS + tid;
            if (fr < n) {
                unsigned long long best = min(wk[tid][0], wk[tid][1]);
                atomicMin(&g_fbest[g_fixrows[fr]], best);
            }
        }
    }
}

// ===== launch #7: apply fixups + gather codes =====
__global__ void gather_kernel(const float* __restrict__ cb, float* __restrict__ out) {
    __shared__ int s_idx[4];
    int tid = threadIdx.x;
    int rslot = tid >> 6;
    int row = blockIdx.x * 4 + rslot;
    int c = tid & 63;
    if (c == 0) {
        int idx;
        if (g_isfix[row]) {
            unsigned long long best = g_fbest[row];
            idx = (int)(uint32_t)best;
            out[IDX_OFF + row]  = (float)idx;
            out[DIST_OFF + row] = g_xsq[row] + decf((uint32_t)(best >> 32));
        } else {
            idx = g_idx[row];
        }
        s_idx[rslot] = idx;
    }
    __syncthreads();
    int idx = s_idx[rslot];
    reinterpret_cast<float4*>(out)[(size_t)row * 64 + c] =
        reinterpret_cast<const float4*>(cb)[(size_t)idx * 64 + c];
}

extern "C" void kernel_launch(void* const* d_in, const int* in_sizes, int n_in,
                              void* d_out, int out_size) {
    const float* x  = (const float*)d_in[0];   // z_e_x  [8,4096,256] f32
    const float* cb = (const float*)d_in[1];   // codebook [8192,256] f32
    float* out = (float*)d_out;                // codes | idx | distances (f32)

    cudaFuncSetAttribute(vq_hmma_kernel,
                         cudaFuncAttributeMaxDynamicSharedMemorySize, SMEM_TOTAL);

    init_kernel<<<RTOT / 256, 256>>>();                    // #1
    prep_a_kernel<<<(RTOT * 32) / 256, 256>>>(x);          // #2
    prep_b_kernel<<<(KTOT * 32) / 256, 256>>>(cb);         // #3
    vq_hmma_kernel<<<NCTA, THREADS, SMEM_TOTAL>>>();       // #4  <- ncu capture slot
    final_kernel<<<RTOT / 256, 256>>>(out);                // #5
    fixup_kernel<<<NCTA * KSLICES, 256>>>(x, cb);          // #6
    gather_kernel<<<RTOT / 4, 256>>>(cb, out);             // #7
}

// round 13
// speedup vs baseline: 1.0075x; 1.0075x over previous
#include <cuda_runtime.h>
#include <cuda_fp16.h>
#include <cstdint>

// ===== problem constants =====
#define RTOT  32768
#define CDIM  256
#define KTOT  8192
#define MT    128
#define NT    64               // 32KB B stages
#define KSTEPS 16
#define NUM_MT (RTOT/MT)       // 256
#define NUM_NT (KTOT/NT)       // 128
#define JOBS  (NUM_MT*NUM_NT)  // 32768
#define NCTA  148
#define THREADS 256

#define SMEM_A    0
#define SMEM_B    65536        // 4 stages x 32KB
#define SMEM_BAR  196608
#define SMEM_TOTAL 196736

#define IDX_OFF  8388608
#define DIST_OFF (8388608+32768)

#define VOFF 1024.0f
#define MARGIN 0.09f
#define FIXROWS 16
#define KSLICES 8

// ===== device globals (static scratch) =====
__device__ uint4 g_Aimg[(size_t)NUM_MT*4096];
__device__ uint4 g_Bimg[(size_t)NUM_NT*2048];
__device__ float g_cbsq[KTOT];
__device__ float g_cbsqo[KTOT];
__device__ float g_xsq[RTOT];
__device__ int   g_idx[RTOT];
__device__ unsigned long long g_best[RTOT];
__device__ unsigned int g_best2[RTOT];
__device__ int g_fixcnt;
__device__ int g_fixrows[RTOT];
__device__ int g_isfix[RTOT];
__device__ unsigned long long g_fbest[RTOT];

// ===== helpers =====
__device__ __forceinline__ uint32_t smem_u32(const void* p) {
    uint32_t a;
    asm("{ .reg .u64 t; cvta.to.shared.u64 t, %1; cvt.u32.u64 %0, t; }" : "=r"(a) : "l"(p));
    return a;
}
__device__ __forceinline__ void cp_async16(uint32_t sa, const void* g) {
    asm volatile("cp.async.cg.shared.global [%0], [%1], 16;" :: "r"(sa), "l"(g));
}
#define CP_COMMIT() asm volatile("cp.async.commit_group;" ::: "memory")
#define CP_WAIT(N)  asm volatile("cp.async.wait_group %0;" :: "n"(N) : "memory")

#define MBARRIER_INIT(mb, c) asm volatile("mbarrier.init.shared.b64 [%0], %1;" :: "r"((uint32_t)(mb)), "r"((uint32_t)(c)) : "memory")
#define MBARRIER_ARRIVE(mb)  asm volatile("mbarrier.arrive.shared.b64 _, [%0];" :: "r"((uint32_t)(mb)) : "memory")
#define CP_ASYNC_MBAR_ARRIVE(mb) asm volatile("cp.async.mbarrier.arrive.noinc.shared.b64 [%0];" :: "r"((uint32_t)(mb)) : "memory")

#define MBAR_WAIT(mb, par) do {                                                   \
    uint32_t _m = (uint32_t)(mb), _p = (uint32_t)(par), _d;                       \
    asm volatile("{\n\t.reg .pred p;\n\t"                                         \
        "mbarrier.try_wait.parity.acquire.cta.shared::cta.b64 p, [%1], %2;\n\t"   \
        "selp.b32 %0,1,0,p;\n\t}" : "=r"(_d) : "r"(_m), "r"(_p) : "memory");      \
    if (!_d) {                                                                    \
        asm volatile("{\n\t.reg .pred P1;\n\t"                                    \
        "WL_%=:\n\t"                                                              \
        "mbarrier.try_wait.parity.acquire.cta.shared::cta.b64 P1, [%0], %1, 0x989680;\n\t" \
        "@P1 bra.uni WD_%=;\n\t"                                                  \
        "bra.uni WL_%=;\n\t"                                                      \
        "WD_%=:\n\t}" :: "r"(_m), "r"(_p) : "memory");                            \
    }                                                                             \
} while (0)

__device__ __forceinline__ void ldsm4(uint32_t* r, uint32_t addr) {
    asm volatile("ldmatrix.sync.aligned.m8n8.x4.shared.b16 {%0,%1,%2,%3}, [%4];"
        : "=r"(r[0]), "=r"(r[1]), "=r"(r[2]), "=r"(r[3]) : "r"(addr));
}
__device__ __forceinline__ void mma16816(float* c, const uint32_t* a, uint32_t b0, uint32_t b1) {
    asm volatile("mma.sync.aligned.m16n8k16.row.col.f32.f16.f16.f32 "
        "{%0,%1,%2,%3}, {%4,%5,%6,%7}, {%8,%9}, {%0,%1,%2,%3};"
        : "+f"(c[0]), "+f"(c[1]), "+f"(c[2]), "+f"(c[3])
        : "r"(a[0]), "r"(a[1]), "r"(a[2]), "r"(a[3]), "r"(b0), "r"(b1));
}
__device__ __forceinline__ uint32_t encf(float f) {
    uint32_t u = __float_as_uint(f);
    return (u & 0x80000000u) ? ~u : (u | 0x80000000u);
}
__device__ __forceinline__ float decf(uint32_t e) {
    uint32_t u = (e & 0x80000000u) ? (e & 0x7fffffffu) : ~e;
    return __uint_as_float(u);
}
__device__ __forceinline__ uint32_t packh2(__half a, __half b) {
    __half2 h = __halves2half2(a, b);
    return *reinterpret_cast<uint32_t*>(&h);
}

// ===== launch #1: init =====
__global__ void init_kernel() {
    int i = blockIdx.x * 256 + threadIdx.x;
    g_best[i] = ~0ull;
    g_best2[i] = 0xFFFFFFFFu;
    g_isfix[i] = 0;
    g_fbest[i] = ~0ull;
    if (i == 0) g_fixcnt = 0;
}

// ===== launches #2/#3: prep =====
__global__ void prep_a_kernel(const float* __restrict__ x) {
    int t = blockIdx.x * 256 + threadIdx.x;
    int row = t >> 5, u = t & 31;
    int ks = u >> 1, kh = u & 1;
    const float* r = x + (size_t)row * CDIM + ks * 16 + kh * 8;
    float s = 0.f;
    __half h[8];
#pragma unroll
    for (int i = 0; i < 8; ++i) { float v = r[i]; s = fmaf(v, v, s); h[i] = __float2half(v); }
    uint4 val;
    val.x = packh2(h[0], h[1]); val.y = packh2(h[2], h[3]);
    val.z = packh2(h[4], h[5]); val.w = packh2(h[6], h[7]);
    int tile = row >> 7, rl = row & 127;
    int phys = (rl * 2 + kh) ^ ((rl >> 2) & 1);
    g_Aimg[(size_t)tile * 4096 + ks * 256 + phys] = val;
#pragma unroll
    for (int o = 16; o; o >>= 1) s += __shfl_xor_sync(0xffffffffu, s, o);
    if ((t & 31) == 0) g_xsq[row] = s;
}
__global__ void prep_b_kernel(const float* __restrict__ cb) {
    int t = blockIdx.x * 256 + threadIdx.x;
    int row = t >> 5, u = t & 31;
    int ks = u >> 1, kh = u & 1;
    const float* r = cb + (size_t)row * CDIM + ks * 16 + kh * 8;
    float s = 0.f;
    __half h[8];
#pragma unroll
    for (int i = 0; i < 8; ++i) { float v = r[i]; s = fmaf(v, v, s); h[i] = __float2half(v); }
    uint4 val;
    val.x = packh2(h[0], h[1]); val.y = packh2(h[2], h[3]);
    val.z = packh2(h[4], h[5]); val.w = packh2(h[6], h[7]);
    int nt = row >> 6, rl = row & 63;
    int phys = (rl * 2 + kh) ^ ((rl >> 2) & 1);
    g_Bimg[(size_t)nt * 2048 + ks * 128 + phys] = val;
#pragma unroll
    for (int o = 16; o; o >>= 1) s += __shfl_xor_sync(0xffffffffu, s, o);
    if ((t & 31) == 0) { g_cbsq[row] = s; g_cbsqo[row] = s + VOFF; }
}

// ===== launch #4: main HMMA kernel — A-stationary in registers =====
__device__ __forceinline__ void issue_A(uint32_t smemA, int m, int tid) {
    const uint4* src = g_Aimg + (size_t)m * 4096 + tid;
#pragma unroll
    for (int i = 0; i < 16; ++i)
        cp_async16(smemA + (tid + i * 256) * 16, src + i * 256);
}
__device__ __forceinline__ void produce_stage(uint32_t smB, uint32_t bar, int jpi, int j, int tid) {
    int sp = jpi & 3;
    int par = (((jpi >> 2) & 1) ^ 1);
    MBAR_WAIT(bar + 32 + sp * 8, par);             // empty[sp]
    const uint4* src = g_Bimg + (size_t)(j & (NUM_NT - 1)) * 2048 + tid;
    uint32_t dst = smB + sp * 32768 + tid * 16;
#pragma unroll
    for (int i = 0; i < 8; ++i)
        cp_async16(dst + i * 4096, src + i * 256);
    CP_ASYNC_MBAR_ARRIVE(bar + sp * 8);            // full[sp]
}

__global__ __launch_bounds__(THREADS, 1)
void vq_hmma_kernel() {
    extern __shared__ char smem[];
    uint32_t sb = smem_u32(smem);
    uint32_t smA = sb + SMEM_A;
    uint32_t smB = sb + SMEM_B;
    uint32_t bar = sb + SMEM_BAR;

    int tid = threadIdx.x;
    int l = tid & 31, w = tid >> 5;
    int wm = w >> 1, wn = w & 1;     // wm: 4 row-slices of 32; wn: 2 col-halves of 32

    uint32_t aoff[2], boff[2];
#pragma unroll
    for (int mt = 0; mt < 2; ++mt) {
        int row = wm * 32 + mt * 16 + (l & 15);
        int kh = l >> 4;
        aoff[mt] = (uint32_t)(((row * 2 + kh) ^ ((row >> 2) & 1)) << 4);
    }
#pragma unroll
    for (int g = 0; g < 2; ++g) {
        int code = wn * 32 + g * 16 + (l & 7) + ((l >> 4) << 3);
        int kh = (l >> 3) & 1;
        boff[g] = (uint32_t)(((code * 2 + kh) ^ ((code >> 2) & 1)) << 4);
    }

    int start = (int)(((long long)blockIdx.x * JOBS) / NCTA);
    int end   = (int)(((long long)(blockIdx.x + 1) * JOBS) / NCTA);
    int njobs = end - start;

    if (tid == 0) {
#pragma unroll
        for (int s = 0; s < 4; ++s) {
            MBARRIER_INIT(bar + s * 8, 256);        // full
            MBARRIER_INIT(bar + 32 + s * 8, 256);   // empty
        }
    }
    __syncthreads();

    int cur_m = start >> 7;
    issue_A(smA, cur_m, tid); CP_COMMIT();
#pragma unroll
    for (int p = 0; p < 3; ++p)
        if (p < njobs) produce_stage(smB, bar, p, start + p, tid);
    CP_WAIT(0);
    __syncthreads();

    // ---- A-stationary: all 32 fragments (16 ksteps x 2 mt) in registers ----
    uint32_t areg[KSTEPS][2][4];
#pragma unroll
    for (int ks = 0; ks < KSTEPS; ++ks) {
        ldsm4(areg[ks][0], smA + ks * 4096 + aoff[0]);
        ldsm4(areg[ks][1], smA + ks * 4096 + aoff[1]);
    }

    float rb[2][2] = {{3.4e38f,3.4e38f},{3.4e38f,3.4e38f}};
    float rs[2][2] = {{3.4e38f,3.4e38f},{3.4e38f,3.4e38f}};
    int   ri[2][2] = {{0,0},{0,0}};

    for (int ji = 0; ji < njobs; ++ji) {
        int j = start + ji;
        int ntj = j & (NUM_NT - 1);
        int s = ji & 3;

        MBAR_WAIT(bar + s * 8, (ji >> 2) & 1);      // full[s]

        float qv[8];
        int qbase = ntj * NT + wn * 32 + (l & 3) * 2;
#pragma unroll
        for (int nb = 0; nb < 4; ++nb) {
            qv[nb * 2]     = __ldg(&g_cbsqo[qbase + nb * 8]);
            qv[nb * 2 + 1] = __ldg(&g_cbsqo[qbase + nb * 8 + 1]);
        }

        float acc[2][4][4];
#pragma unroll
        for (int mt = 0; mt < 2; ++mt)
#pragma unroll
            for (int nb = 0; nb < 4; ++nb)
#pragma unroll
                for (int q = 0; q < 4; ++q) acc[mt][nb][q] = 0.f;

        uint32_t Bstage = smB + s * 32768;
#pragma unroll
        for (int ks = 0; ks < KSTEPS; ++ks) {
            uint32_t Bpan = Bstage + ks * 2048;
            uint32_t bf[2][4];
            ldsm4(bf[0], Bpan + boff[0]);
            ldsm4(bf[1], Bpan + boff[1]);
#pragma unroll
            for (int mt = 0; mt < 2; ++mt)
#pragma unroll
                for (int g = 0; g < 2; ++g) {
                    mma16816(acc[mt][g*2  ], areg[ks][mt], bf[g][0], bf[g][1]);
                    mma16816(acc[mt][g*2+1], areg[ks][mt], bf[g][2], bf[g][3]);
                }
        }

        MBARRIER_ARRIVE(bar + 32 + s * 8);          // empty[s]

        // epilogue (registers only)
#pragma unroll
        for (int mt = 0; mt < 2; ++mt)
#pragma unroll
            for (int h = 0; h < 2; ++h) {
                uint32_t k1 = 0xFFFFFFFFu, k2 = 0xFFFFFFFFu;
#pragma unroll
                for (int nb = 0; nb < 4; ++nb)
#pragma unroll
                    for (int c = 0; c < 2; ++c) {
                        float v = fmaf(-2.f, acc[mt][nb][h * 2 + c], qv[nb * 2 + c]);
                        uint32_t k = (__float_as_uint(v) & 0xFFFFFFF8u) | (uint32_t)(nb * 2 + c);
                        uint32_t t = max(k1, k);
                        k1 = min(k1, k);
                        k2 = min(k2, t);
                    }
                float v1 = __uint_as_float(k1 & 0xFFFFFFF8u);
                float v2 = __uint_as_float(k2 & 0xFFFFFFF8u);
                int li = (int)(k1 & 7u);
                int gidx = qbase + (li >> 1) * 8 + (li & 1);
                if (v1 < rb[mt][h]) {
                    rs[mt][h] = fminf(rb[mt][h], v2);
                    rb[mt][h] = v1; ri[mt][h] = gidx;
                } else {
                    rs[mt][h] = fminf(rs[mt][h], v1);
                }
            }

        int jn = j + 1;
        bool m_change = (jn < end) && ((jn >> 7) != cur_m);
        if (m_change || jn == end) {
#pragma unroll
            for (int mt = 0; mt < 2; ++mt)
#pragma unroll
                for (int h = 0; h < 2; ++h) {
                    float bv = rb[mt][h], sv = rs[mt][h];
                    int bi = ri[mt][h];
#pragma unroll
                    for (int o = 1; o < 4; o <<= 1) {
                        float ov = __shfl_xor_sync(0xffffffffu, bv, o);
                        int   oi = __shfl_xor_sync(0xffffffffu, bi, o);
                        float os = __shfl_xor_sync(0xffffffffu, sv, o);
                        if (ov < bv || (ov == bv && oi < bi)) {
                            sv = fminf(bv, os); bv = ov; bi = oi;
                        } else {
                            sv = fminf(sv, ov);
                        }
                    }
                    if ((l & 3) == 0) {
                        int r = cur_m * MT + wm * 32 + mt * 16 + h * 8 + (l >> 2);
                        unsigned long long key =
                            ((unsigned long long)encf(bv) << 32) | (uint32_t)bi;
                        unsigned long long old = atomicMin(&g_best[r], key);
                        uint32_t oldenc = (uint32_t)(old >> 32);
                        uint32_t be = encf(bv);
                        uint32_t cand = min(encf(sv), max(be, oldenc));
                        atomicMin(&g_best2[r], cand);
                    }
                    rb[mt][h] = 3.4e38f; rs[mt][h] = 3.4e38f; ri[mt][h] = 0;
                }
        }

        if (ji + 3 < njobs) produce_stage(smB, bar, ji + 3, start + ji + 3, tid);

        if (m_change) {
            cur_m = jn >> 7;
            __syncthreads();                        // all warps done reading smA
            issue_A(smA, cur_m, tid); CP_COMMIT();
            CP_WAIT(0);
            __syncthreads();                        // new A visible
#pragma unroll
            for (int ks = 0; ks < KSTEPS; ++ks) {   // refill stationary A regs
                ldsm4(areg[ks][0], smA + ks * 4096 + aoff[0]);
                ldsm4(areg[ks][1], smA + ks * 4096 + aoff[1]);
            }
        }
    }
}

// ===== launch #5: finalize, flag close rows =====
__global__ void final_kernel(float* __restrict__ out) {
    int i = blockIdx.x * 256 + threadIdx.x;
    unsigned long long key = g_best[i];
    int idx = (int)(uint32_t)key;
    float val = decf((uint32_t)(key >> 32)) - VOFF;
    float sec = decf(g_best2[i]) - VOFF;
    out[IDX_OFF + i]  = (float)idx;
    out[DIST_OFF + i] = g_xsq[i] + val;
    g_idx[i] = idx;
    if (sec - val < MARGIN) {
        g_isfix[i] = 1;
        int p = atomicAdd(&g_fixcnt, 1);
        g_fixrows[p] = i;
    }
}

// ===== launch #6: exact fp32 rescan, K-sliced 8-way =====
__global__ __launch_bounds__(256) void fixup_kernel(const float* __restrict__ x,
                                                    const float* __restrict__ cb) {
    __shared__ float4 xs[FIXROWS][64];
    __shared__ unsigned long long wk[FIXROWS][2];
    int tid = threadIdx.x;
    int n = g_fixcnt;
    int ngroups = (n + FIXROWS - 1) / FIXROWS;
    int slice = blockIdx.x & (KSLICES - 1);
    int g0 = blockIdx.x >> 3;
    const float4* c4 = reinterpret_cast<const float4*>(cb);
    for (int g = g0; g < ngroups; g += NCTA) {
        __syncthreads();
        for (int i = tid; i < FIXROWS * 64; i += 256) {
            int r = i >> 6, q = i & 63;
            int fr = g * FIXROWS + r;
            int row = g_fixrows[(fr < n) ? fr : g * FIXROWS];
            xs[r][q] = reinterpret_cast<const float4*>(x)[(size_t)row * 64 + q];
        }
        __syncthreads();
        int rg = tid >> 6;
        int cg = tid & 63;
        float bv[4] = {3.4e38f,3.4e38f,3.4e38f,3.4e38f};
        int   bi[4] = {0,0,0,0};
        for (int k = slice * 4; k < slice * 4 + 4; ++k) {
            int c0 = k * 256 + cg * 4;
            float acc[4][4];
#pragma unroll
            for (int r = 0; r < 4; ++r)
#pragma unroll
                for (int cc = 0; cc < 4; ++cc) acc[r][cc] = 0.f;
#pragma unroll 8
            for (int q = 0; q < 64; ++q) {
                float4 xv[4];
#pragma unroll
                for (int r = 0; r < 4; ++r) xv[r] = xs[rg * 4 + r][q];
#pragma unroll
                for (int cc = 0; cc < 4; ++cc) {
                    float4 v = c4[(size_t)(c0 + cc) * 64 + q];
#pragma unroll
                    for (int r = 0; r < 4; ++r) {
                        acc[r][cc] = fmaf(v.x, xv[r].x, acc[r][cc]);
                        acc[r][cc] = fmaf(v.y, xv[r].y, acc[r][cc]);
                        acc[r][cc] = fmaf(v.z, xv[r].z, acc[r][cc]);
                        acc[r][cc] = fmaf(v.w, xv[r].w, acc[r][cc]);
                    }
                }
            }
#pragma unroll
            for (int cc = 0; cc < 4; ++cc) {
                float cq = __ldg(&g_cbsq[c0 + cc]);
#pragma unroll
                for (int r = 0; r < 4; ++r) {
                    float val = fmaf(-2.f, acc[r][cc], cq);
                    if (val < bv[r] || (val == bv[r] && c0 + cc < bi[r])) {
                        bv[r] = val; bi[r] = c0 + cc;
                    }
                }
            }
        }
#pragma unroll
        for (int r = 0; r < 4; ++r) {
            unsigned long long key =
                ((unsigned long long)encf(bv[r]) << 32) | (uint32_t)bi[r];
#pragma unroll
            for (int o = 16; o; o >>= 1) {
                unsigned long long ok = __shfl_xor_sync(0xffffffffu, key, o);
                key = min(key, ok);
            }
            if ((tid & 31) == 0) wk[rg * 4 + r][(tid >> 5) & 1] = key;
        }
        __syncthreads();
        if (tid < FIXROWS) {
            int fr = g * FIXROWS + tid;
            if (fr < n) {
                unsigned long long best = min(wk[tid][0], wk[tid][1]);
                atomicMin(&g_fbest[g_fixrows[fr]], best);
            }
        }
    }
}

// ===== launch #7: apply fixups + gather codes =====
__global__ void gather_kernel(const float* __restrict__ cb, float* __restrict__ out) {
    __shared__ int s_idx[4];
    int tid = threadIdx.x;
    int rslot = tid >> 6;
    int row = blockIdx.x * 4 + rslot;
    int c = tid & 63;
    if (c == 0) {
        int idx;
        if (g_isfix[row]) {
            unsigned long long best = g_fbest[row];
            idx = (int)(uint32_t)best;
            out[IDX_OFF + row]  = (float)idx;
            out[DIST_OFF + row] = g_xsq[row] + decf((uint32_t)(best >> 32));
        } else {
            idx = g_idx[row];
        }
        s_idx[rslot] = idx;
    }
    __syncthreads();
    int idx = s_idx[rslot];
    reinterpret_cast<float4*>(out)[(size_t)row * 64 + c] =
        reinterpret_cast<const float4*>(cb)[(size_t)idx * 64 + c];
}

extern "C" void kernel_launch(void* const* d_in, const int* in_sizes, int n_in,
                              void* d_out, int out_size) {
    const float* x  = (const float*)d_in[0];   // z_e_x  [8,4096,256] f32
    const float* cb = (const float*)d_in[1];   // codebook [8192,256] f32
    float* out = (float*)d_out;                // codes | idx | distances (f32)

    cudaFuncSetAttribute(vq_hmma_kernel,
                         cudaFuncAttributeMaxDynamicSharedMemorySize, SMEM_TOTAL);

    init_kernel<<<RTOT / 256, 256>>>();                    // #1
    prep_a_kernel<<<(RTOT * 32) / 256, 256>>>(x);          // #2
    prep_b_kernel<<<(KTOT * 32) / 256, 256>>>(cb);         // #3
    vq_hmma_kernel<<<NCTA, THREADS, SMEM_TOTAL>>>();       // #4  <- ncu capture slot
    final_kernel<<<RTOT / 256, 256>>>(out);                // #5
    fixup_kernel<<<NCTA * KSLICES, 256>>>(x, cb);          // #6
    gather_kernel<<<RTOT / 4, 256>>>(cb, out);             // #7
}

// round 14
// speedup vs baseline: 1.0224x; 1.0148x over previous
#include <cuda_runtime.h>
#include <cuda_fp16.h>
#include <cstdint>

// ===== problem constants =====
#define RTOT  32768
#define CDIM  256
#define KTOT  8192
#define MT    128
#define NT    64               // 32KB B stages
#define KSTEPS 16
#define NUM_MT (RTOT/MT)       // 256
#define NUM_NT (KTOT/NT)       // 128
#define JOBS  (NUM_MT*NUM_NT)  // 32768
#define NCTA  148
#define THREADS 512            // 16 warps, 4 per SMSP

#define SMEM_A    0
#define SMEM_B    65536        // 4 stages x 32KB
#define SMEM_BAR  196608
#define SMEM_TOTAL 196736

#define IDX_OFF  8388608
#define DIST_OFF (8388608+32768)

#define VOFF 1024.0f
#define MARGIN 0.09f
#define FIXROWS 16
#define KSLICES 8

// ===== device globals (static scratch) =====
__device__ uint4 g_Aimg[(size_t)NUM_MT*4096];
__device__ uint4 g_Bimg[(size_t)NUM_NT*2048];
__device__ float g_cbsq[KTOT];
__device__ float g_cbsqo[KTOT];
__device__ float g_xsq[RTOT];
__device__ int   g_idx[RTOT];
__device__ unsigned long long g_best[RTOT];
__device__ unsigned int g_best2[RTOT];
__device__ int g_fixcnt;
__device__ int g_fixrows[RTOT];
__device__ int g_isfix[RTOT];
__device__ unsigned long long g_fbest[RTOT];

// ===== helpers =====
__device__ __forceinline__ uint32_t smem_u32(const void* p) {
    uint32_t a;
    asm("{ .reg .u64 t; cvta.to.shared.u64 t, %1; cvt.u32.u64 %0, t; }" : "=r"(a) : "l"(p));
    return a;
}
__device__ __forceinline__ void cp_async16(uint32_t sa, const void* g) {
    asm volatile("cp.async.cg.shared.global [%0], [%1], 16;" :: "r"(sa), "l"(g));
}
#define CP_COMMIT() asm volatile("cp.async.commit_group;" ::: "memory")
#define CP_WAIT(N)  asm volatile("cp.async.wait_group %0;" :: "n"(N) : "memory")

#define MBARRIER_INIT(mb, c) asm volatile("mbarrier.init.shared.b64 [%0], %1;" :: "r"((uint32_t)(mb)), "r"((uint32_t)(c)) : "memory")
#define MBARRIER_ARRIVE(mb)  asm volatile("mbarrier.arrive.shared.b64 _, [%0];" :: "r"((uint32_t)(mb)) : "memory")
#define CP_ASYNC_MBAR_ARRIVE(mb) asm volatile("cp.async.mbarrier.arrive.noinc.shared.b64 [%0];" :: "r"((uint32_t)(mb)) : "memory")

#define MBAR_WAIT(mb, par) do {                                                   \
    uint32_t _m = (uint32_t)(mb), _p = (uint32_t)(par), _d;                       \
    asm volatile("{\n\t.reg .pred p;\n\t"                                         \
        "mbarrier.try_wait.parity.acquire.cta.shared::cta.b64 p, [%1], %2;\n\t"   \
        "selp.b32 %0,1,0,p;\n\t}" : "=r"(_d) : "r"(_m), "r"(_p) : "memory");      \
    if (!_d) {                                                                    \
        asm volatile("{\n\t.reg .pred P1;\n\t"                                    \
        "WL_%=:\n\t"                                                              \
        "mbarrier.try_wait.parity.acquire.cta.shared::cta.b64 P1, [%0], %1, 0x989680;\n\t" \
        "@P1 bra.uni WD_%=;\n\t"                                                  \
        "bra.uni WL_%=;\n\t"                                                      \
        "WD_%=:\n\t}" :: "r"(_m), "r"(_p) : "memory");                            \
    }                                                                             \
} while (0)

__device__ __forceinline__ void ldsm4(uint32_t* r, uint32_t addr) {
    asm volatile("ldmatrix.sync.aligned.m8n8.x4.shared.b16 {%0,%1,%2,%3}, [%4];"
        : "=r"(r[0]), "=r"(r[1]), "=r"(r[2]), "=r"(r[3]) : "r"(addr));
}
__device__ __forceinline__ void mma16816(float* c, const uint32_t* a, uint32_t b0, uint32_t b1) {
    asm volatile("mma.sync.aligned.m16n8k16.row.col.f32.f16.f16.f32 "
        "{%0,%1,%2,%3}, {%4,%5,%6,%7}, {%8,%9}, {%0,%1,%2,%3};"
        : "+f"(c[0]), "+f"(c[1]), "+f"(c[2]), "+f"(c[3])
        : "r"(a[0]), "r"(a[1]), "r"(a[2]), "r"(a[3]), "r"(b0), "r"(b1));
}
__device__ __forceinline__ uint32_t encf(float f) {
    uint32_t u = __float_as_uint(f);
    return (u & 0x80000000u) ? ~u : (u | 0x80000000u);
}
__device__ __forceinline__ float decf(uint32_t e) {
    uint32_t u = (e & 0x80000000u) ? (e & 0x7fffffffu) : ~e;
    return __uint_as_float(u);
}
__device__ __forceinline__ uint32_t packh2(__half a, __half b) {
    __half2 h = __halves2half2(a, b);
    return *reinterpret_cast<uint32_t*>(&h);
}

// ===== launch #1: init =====
__global__ void init_kernel() {
    int i = blockIdx.x * 256 + threadIdx.x;
    g_best[i] = ~0ull;
    g_best2[i] = 0xFFFFFFFFu;
    g_isfix[i] = 0;
    g_fbest[i] = ~0ull;
    if (i == 0) g_fixcnt = 0;
}

// ===== launches #2/#3: prep =====
__global__ void prep_a_kernel(const float* __restrict__ x) {
    int t = blockIdx.x * 256 + threadIdx.x;
    int row = t >> 5, u = t & 31;
    int ks = u >> 1, kh = u & 1;
    const float* r = x + (size_t)row * CDIM + ks * 16 + kh * 8;
    float s = 0.f;
    __half h[8];
#pragma unroll
    for (int i = 0; i < 8; ++i) { float v = r[i]; s = fmaf(v, v, s); h[i] = __float2half(v); }
    uint4 val;
    val.x = packh2(h[0], h[1]); val.y = packh2(h[2], h[3]);
    val.z = packh2(h[4], h[5]); val.w = packh2(h[6], h[7]);
    int tile = row >> 7, rl = row & 127;
    int phys = (rl * 2 + kh) ^ ((rl >> 2) & 1);
    g_Aimg[(size_t)tile * 4096 + ks * 256 + phys] = val;
#pragma unroll
    for (int o = 16; o; o >>= 1) s += __shfl_xor_sync(0xffffffffu, s, o);
    if ((t & 31) == 0) g_xsq[row] = s;
}
__global__ void prep_b_kernel(const float* __restrict__ cb) {
    int t = blockIdx.x * 256 + threadIdx.x;
    int row = t >> 5, u = t & 31;
    int ks = u >> 1, kh = u & 1;
    const float* r = cb + (size_t)row * CDIM + ks * 16 + kh * 8;
    float s = 0.f;
    __half h[8];
#pragma unroll
    for (int i = 0; i < 8; ++i) { float v = r[i]; s = fmaf(v, v, s); h[i] = __float2half(v); }
    uint4 val;
    val.x = packh2(h[0], h[1]); val.y = packh2(h[2], h[3]);
    val.z = packh2(h[4], h[5]); val.w = packh2(h[6], h[7]);
    int nt = row >> 6, rl = row & 63;
    int phys = (rl * 2 + kh) ^ ((rl >> 2) & 1);
    g_Bimg[(size_t)nt * 2048 + ks * 128 + phys] = val;
#pragma unroll
    for (int o = 16; o; o >>= 1) s += __shfl_xor_sync(0xffffffffu, s, o);
    if ((t & 31) == 0) { g_cbsq[row] = s; g_cbsqo[row] = s + VOFF; }
}

// ===== launch #4: main HMMA kernel — A-stationary, 512 threads, mbarrier ring =====
__device__ __forceinline__ void issue_A(uint32_t smemA, int m, int tid) {
    const uint4* src = g_Aimg + (size_t)m * 4096 + tid;
#pragma unroll
    for (int i = 0; i < 8; ++i)
        cp_async16(smemA + (tid + i * 512) * 16, src + i * 512);
}
__device__ __forceinline__ void produce_stage(uint32_t smB, uint32_t bar, int jpi, int j, int tid) {
    int sp = jpi & 3;
    int par = (((jpi >> 2) & 1) ^ 1);
    MBAR_WAIT(bar + 32 + sp * 8, par);             // empty[sp]
    const uint4* src = g_Bimg + (size_t)(j & (NUM_NT - 1)) * 2048 + tid;
    uint32_t dst = smB + sp * 32768 + tid * 16;
#pragma unroll
    for (int i = 0; i < 4; ++i)
        cp_async16(dst + i * 8192, src + i * 512);
    CP_ASYNC_MBAR_ARRIVE(bar + sp * 8);            // full[sp]
}

__global__ __launch_bounds__(THREADS, 1)
void vq_hmma_kernel() {
    extern __shared__ char smem[];
    uint32_t sb = smem_u32(smem);
    uint32_t smA = sb + SMEM_A;
    uint32_t smB = sb + SMEM_B;
    uint32_t bar = sb + SMEM_BAR;

    int tid = threadIdx.x;
    int l = tid & 31, w = tid >> 5;
    int wm = w >> 1, wn = w & 1;     // wm: 8 row-slices of 16; wn: 2 col-halves of 32

    uint32_t aoff, boff[2];
    {
        int row = wm * 16 + (l & 15);
        int kh = l >> 4;
        aoff = (uint32_t)(((row * 2 + kh) ^ ((row >> 2) & 1)) << 4);
    }
#pragma unroll
    for (int g = 0; g < 2; ++g) {
        int code = wn * 32 + g * 16 + (l & 7) + ((l >> 4) << 3);
        int kh = (l >> 3) & 1;
        boff[g] = (uint32_t)(((code * 2 + kh) ^ ((code >> 2) & 1)) << 4);
    }

    int start = (int)(((long long)blockIdx.x * JOBS) / NCTA);
    int end   = (int)(((long long)(blockIdx.x + 1) * JOBS) / NCTA);
    int njobs = end - start;

    if (tid == 0) {
#pragma unroll
        for (int s = 0; s < 4; ++s) {
            MBARRIER_INIT(bar + s * 8, 512);        // full
            MBARRIER_INIT(bar + 32 + s * 8, 512);   // empty
        }
    }
    __syncthreads();

    int cur_m = start >> 7;
    issue_A(smA, cur_m, tid); CP_COMMIT();
#pragma unroll
    for (int p = 0; p < 3; ++p)
        if (p < njobs) produce_stage(smB, bar, p, start + p, tid);
    CP_WAIT(0);
    __syncthreads();

    // ---- A-stationary: 16 fragments (16 ksteps x 1 slice) = 64 regs ----
    uint32_t areg[KSTEPS][4];
#pragma unroll
    for (int ks = 0; ks < KSTEPS; ++ks)
        ldsm4(areg[ks], smA + ks * 4096 + aoff);

    float rb[2] = {3.4e38f, 3.4e38f};
    float rs[2] = {3.4e38f, 3.4e38f};
    int   ri[2] = {0, 0};

    for (int ji = 0; ji < njobs; ++ji) {
        int j = start + ji;
        int ntj = j & (NUM_NT - 1);
        int s = ji & 3;

        MBAR_WAIT(bar + s * 8, (ji >> 2) & 1);      // full[s]

        float qv[8];
        int qbase = ntj * NT + wn * 32 + (l & 3) * 2;
#pragma unroll
        for (int nb = 0; nb < 4; ++nb) {
            qv[nb * 2]     = __ldg(&g_cbsqo[qbase + nb * 8]);
            qv[nb * 2 + 1] = __ldg(&g_cbsqo[qbase + nb * 8 + 1]);
        }

        float acc[4][4];
#pragma unroll
        for (int nb = 0; nb < 4; ++nb)
#pragma unroll
            for (int q = 0; q < 4; ++q) acc[nb][q] = 0.f;

        uint32_t Bstage = smB + s * 32768;
#pragma unroll
        for (int ks = 0; ks < KSTEPS; ++ks) {
            uint32_t Bpan = Bstage + ks * 2048;
            uint32_t bf[2][4];
            ldsm4(bf[0], Bpan + boff[0]);
            ldsm4(bf[1], Bpan + boff[1]);
#pragma unroll
            for (int g = 0; g < 2; ++g) {
                mma16816(acc[g*2  ], areg[ks], bf[g][0], bf[g][1]);
                mma16816(acc[g*2+1], areg[ks], bf[g][2], bf[g][3]);
            }
        }

        MBARRIER_ARRIVE(bar + 32 + s * 8);          // empty[s]

        // epilogue (registers only)
#pragma unroll
        for (int h = 0; h < 2; ++h) {
            uint32_t k1 = 0xFFFFFFFFu, k2 = 0xFFFFFFFFu;
#pragma unroll
            for (int nb = 0; nb < 4; ++nb)
#pragma unroll
                for (int c = 0; c < 2; ++c) {
                    float v = fmaf(-2.f, acc[nb][h * 2 + c], qv[nb * 2 + c]);
                    uint32_t k = (__float_as_uint(v) & 0xFFFFFFF8u) | (uint32_t)(nb * 2 + c);
                    uint32_t t = max(k1, k);
                    k1 = min(k1, k);
                    k2 = min(k2, t);
                }
            float v1 = __uint_as_float(k1 & 0xFFFFFFF8u);
            float v2 = __uint_as_float(k2 & 0xFFFFFFF8u);
            int li = (int)(k1 & 7u);
            int gidx = qbase + (li >> 1) * 8 + (li & 1);
            if (v1 < rb[h]) {
                rs[h] = fminf(rb[h], v2);
                rb[h] = v1; ri[h] = gidx;
            } else {
                rs[h] = fminf(rs[h], v1);
            }
        }

        int jn = j + 1;
        bool m_change = (jn < end) && ((jn >> 7) != cur_m);
        if (m_change || jn == end) {
#pragma unroll
            for (int h = 0; h < 2; ++h) {
                float bv = rb[h], sv = rs[h];
                int bi = ri[h];
#pragma unroll
                for (int o = 1; o < 4; o <<= 1) {
                    float ov = __shfl_xor_sync(0xffffffffu, bv, o);
                    int   oi = __shfl_xor_sync(0xffffffffu, bi, o);
                    float os = __shfl_xor_sync(0xffffffffu, sv, o);
                    if (ov < bv || (ov == bv && oi < bi)) {
                        sv = fminf(bv, os); bv = ov; bi = oi;
                    } else {
                        sv = fminf(sv, ov);
                    }
                }
                if ((l & 3) == 0) {
                    int r = cur_m * MT + wm * 16 + h * 8 + (l >> 2);
                    unsigned long long key =
                        ((unsigned long long)encf(bv) << 32) | (uint32_t)bi;
                    unsigned long long old = atomicMin(&g_best[r], key);
                    uint32_t oldenc = (uint32_t)(old >> 32);
                    uint32_t be = encf(bv);
                    uint32_t cand = min(encf(sv), max(be, oldenc));
                    atomicMin(&g_best2[r], cand);
                }
                rb[h] = 3.4e38f; rs[h] = 3.4e38f; ri[h] = 0;
            }
        }

        if (ji + 3 < njobs) produce_stage(smB, bar, ji + 3, start + ji + 3, tid);

        if (m_change) {
            cur_m = jn >> 7;
            __syncthreads();                        // all warps done reading smA
            issue_A(smA, cur_m, tid); CP_COMMIT();
            CP_WAIT(0);
            __syncthreads();                        // new A visible
#pragma unroll
            for (int ks = 0; ks < KSTEPS; ++ks)     // refill stationary A regs
                ldsm4(areg[ks], smA + ks * 4096 + aoff);
        }
    }
}

// ===== launch #5: finalize, flag close rows =====
__global__ void final_kernel(float* __restrict__ out) {
    int i = blockIdx.x * 256 + threadIdx.x;
    unsigned long long key = g_best[i];
    int idx = (int)(uint32_t)key;
    float val = decf((uint32_t)(key >> 32)) - VOFF;
    float sec = decf(g_best2[i]) - VOFF;
    out[IDX_OFF + i]  = (float)idx;
    out[DIST_OFF + i] = g_xsq[i] + val;
    g_idx[i] = idx;
    if (sec - val < MARGIN) {
        g_isfix[i] = 1;
        int p = atomicAdd(&g_fixcnt, 1);
        g_fixrows[p] = i;
    }
}

// ===== launch #6: exact fp32 rescan, K-sliced 8-way =====
__global__ __launch_bounds__(256) void fixup_kernel(const float* __restrict__ x,
                                                    const float* __restrict__ cb) {
    __shared__ float4 xs[FIXROWS][64];
    __shared__ unsigned long long wk[FIXROWS][2];
    int tid = threadIdx.x;
    int n = g_fixcnt;
    int ngroups = (n + FIXROWS - 1) / FIXROWS;
    int slice = blockIdx.x & (KSLICES - 1);
    int g0 = blockIdx.x >> 3;
    const float4* c4 = reinterpret_cast<const float4*>(cb);
    for (int g = g0; g < ngroups; g += NCTA) {
        __syncthreads();
        for (int i = tid; i < FIXROWS * 64; i += 256) {
            int r = i >> 6, q = i & 63;
            int fr = g * FIXROWS + r;
            int row = g_fixrows[(fr < n) ? fr : g * FIXROWS];
            xs[r][q] = reinterpret_cast<const float4*>(x)[(size_t)row * 64 + q];
        }
        __syncthreads();
        int rg = tid >> 6;
        int cg = tid & 63;
        float bv[4] = {3.4e38f,3.4e38f,3.4e38f,3.4e38f};
        int   bi[4] = {0,0,0,0};
        for (int k = slice * 4; k < slice * 4 + 4; ++k) {
            int c0 = k * 256 + cg * 4;
            float acc[4][4];
#pragma unroll
            for (int r = 0; r < 4; ++r)
#pragma unroll
                for (int cc = 0; cc < 4; ++cc) acc[r][cc] = 0.f;
#pragma unroll 8
            for (int q = 0; q < 64; ++q) {
                float4 xv[4];
#pragma unroll
                for (int r = 0; r < 4; ++r) xv[r] = xs[rg * 4 + r][q];
#pragma unroll
                for (int cc = 0; cc < 4; ++cc) {
                    float4 v = c4[(size_t)(c0 + cc) * 64 + q];
#pragma unroll
                    for (int r = 0; r < 4; ++r) {
                        acc[r][cc] = fmaf(v.x, xv[r].x, acc[r][cc]);
                        acc[r][cc] = fmaf(v.y, xv[r].y, acc[r][cc]);
                        acc[r][cc] = fmaf(v.z, xv[r].z, acc[r][cc]);
                        acc[r][cc] = fmaf(v.w, xv[r].w, acc[r][cc]);
                    }
                }
            }
#pragma unroll
            for (int cc = 0; cc < 4; ++cc) {
                float cq = __ldg(&g_cbsq[c0 + cc]);
#pragma unroll
                for (int r = 0; r < 4; ++r) {
                    float val = fmaf(-2.f, acc[r][cc], cq);
                    if (val < bv[r] || (val == bv[r] && c0 + cc < bi[r])) {
                        bv[r] = val; bi[r] = c0 + cc;
                    }
                }
            }
        }
#pragma unroll
        for (int r = 0; r < 4; ++r) {
            unsigned long long key =
                ((unsigned long long)encf(bv[r]) << 32) | (uint32_t)bi[r];
#pragma unroll
            for (int o = 16; o; o >>= 1) {
                unsigned long long ok = __shfl_xor_sync(0xffffffffu, key, o);
                key = min(key, ok);
            }
            if ((tid & 31) == 0) wk[rg * 4 + r][(tid >> 5) & 1] = key;
        }
        __syncthreads();
        if (tid < FIXROWS) {
            int fr = g * FIXROWS + tid;
            if (fr < n) {
                unsigned long long best = min(wk[tid][0], wk[tid][1]);
                atomicMin(&g_fbest[g_fixrows[fr]], best);
            }
        }
    }
}

// ===== launch #7: apply fixups + gather codes =====
__global__ void gather_kernel(const float* __restrict__ cb, float* __restrict__ out) {
    __shared__ int s_idx[4];
    int tid = threadIdx.x;
    int rslot = tid >> 6;
    int row = blockIdx.x * 4 + rslot;
    int c = tid & 63;
    if (c == 0) {
        int idx;
        if (g_isfix[row]) {
            unsigned long long best = g_fbest[row];
            idx = (int)(uint32_t)best;
            out[IDX_OFF + row]  = (float)idx;
            out[DIST_OFF + row] = g_xsq[row] + decf((uint32_t)(best >> 32));
        } else {
            idx = g_idx[row];
        }
        s_idx[rslot] = idx;
    }
    __syncthreads();
    int idx = s_idx[rslot];
    reinterpret_cast<float4*>(out)[(size_t)row * 64 + c] =
        reinterpret_cast<const float4*>(cb)[(size_t)idx * 64 + c];
}

extern "C" void kernel_launch(void* const* d_in, const int* in_sizes, int n_in,
                              void* d_out, int out_size) {
    const float* x  = (const float*)d_in[0];   // z_e_x  [8,4096,256] f32
    const float* cb = (const float*)d_in[1];   // codebook [8192,256] f32
    float* out = (float*)d_out;                // codes | idx | distances (f32)

    cudaFuncSetAttribute(vq_hmma_kernel,
                         cudaFuncAttributeMaxDynamicSharedMemorySize, SMEM_TOTAL);

    init_kernel<<<RTOT / 256, 256>>>();                    // #1
    prep_a_kernel<<<(RTOT * 32) / 256, 256>>>(x);          // #2
    prep_b_kernel<<<(KTOT * 32) / 256, 256>>>(cb);         // #3
    vq_hmma_kernel<<<NCTA, THREADS, SMEM_TOTAL>>>();       // #4  <- ncu capture slot
    final_kernel<<<RTOT / 256, 256>>>(out);                // #5
    fixup_kernel<<<NCTA * KSLICES, 256>>>(x, cb);          // #6
    gather_kernel<<<RTOT / 4, 256>>>(cb, out);             // #7
}

// round 15
// speedup vs baseline: 1.0386x; 1.0159x over previous
#include <cuda_runtime.h>
#include <cuda_fp16.h>
#include <cstdint>

// ===== problem constants =====
#define RTOT  32768
#define CDIM  256
#define KTOT  8192
#define MT    128
#define NT    64               // 32KB B stages
#define KSTEPS 16
#define ASTAT 8                // ksteps held stationary in registers
#define NUM_MT (RTOT/MT)       // 256
#define NUM_NT (KTOT/NT)       // 128
#define JOBS  (NUM_MT*NUM_NT)  // 32768
#define NCTA  148
#define THREADS 512            // 16 warps, 4 per SMSP

#define SMEM_A    0
#define SMEM_B    65536        // 4 stages x 32KB
#define SMEM_BAR  196608
#define SMEM_TOTAL 196736

#define IDX_OFF  8388608
#define DIST_OFF (8388608+32768)

#define VOFF 1024.0f
#define MARGIN 0.09f
#define FIXROWS 16
#define KSLICES 8

// ===== device globals (static scratch) =====
__device__ uint4 g_Aimg[(size_t)NUM_MT*4096];
__device__ uint4 g_Bimg[(size_t)NUM_NT*2048];
__device__ float g_cbsq[KTOT];
__device__ float g_cbsqo[KTOT];
__device__ float g_xsq[RTOT];
__device__ int   g_idx[RTOT];
__device__ unsigned long long g_best[RTOT];
__device__ unsigned int g_best2[RTOT];
__device__ int g_fixcnt;
__device__ int g_fixrows[RTOT];
__device__ int g_isfix[RTOT];
__device__ unsigned long long g_fbest[RTOT];

// ===== helpers =====
__device__ __forceinline__ uint32_t smem_u32(const void* p) {
    uint32_t a;
    asm("{ .reg .u64 t; cvta.to.shared.u64 t, %1; cvt.u32.u64 %0, t; }" : "=r"(a) : "l"(p));
    return a;
}
__device__ __forceinline__ void cp_async16(uint32_t sa, const void* g) {
    asm volatile("cp.async.cg.shared.global [%0], [%1], 16;" :: "r"(sa), "l"(g));
}
#define CP_COMMIT() asm volatile("cp.async.commit_group;" ::: "memory")
#define CP_WAIT(N)  asm volatile("cp.async.wait_group %0;" :: "n"(N) : "memory")

#define MBARRIER_INIT(mb, c) asm volatile("mbarrier.init.shared.b64 [%0], %1;" :: "r"((uint32_t)(mb)), "r"((uint32_t)(c)) : "memory")
#define MBARRIER_ARRIVE(mb)  asm volatile("mbarrier.arrive.shared.b64 _, [%0];" :: "r"((uint32_t)(mb)) : "memory")
#define CP_ASYNC_MBAR_ARRIVE(mb) asm volatile("cp.async.mbarrier.arrive.noinc.shared.b64 [%0];" :: "r"((uint32_t)(mb)) : "memory")

#define MBAR_WAIT(mb, par) do {                                                   \
    uint32_t _m = (uint32_t)(mb), _p = (uint32_t)(par), _d;                       \
    asm volatile("{\n\t.reg .pred p;\n\t"                                         \
        "mbarrier.try_wait.parity.acquire.cta.shared::cta.b64 p, [%1], %2;\n\t"   \
        "selp.b32 %0,1,0,p;\n\t}" : "=r"(_d) : "r"(_m), "r"(_p) : "memory");      \
    if (!_d) {                                                                    \
        asm volatile("{\n\t.reg .pred P1;\n\t"                                    \
        "WL_%=:\n\t"                                                              \
        "mbarrier.try_wait.parity.acquire.cta.shared::cta.b64 P1, [%0], %1, 0x989680;\n\t" \
        "@P1 bra.uni WD_%=;\n\t"                                                  \
        "bra.uni WL_%=;\n\t"                                                      \
        "WD_%=:\n\t}" :: "r"(_m), "r"(_p) : "memory");                            \
    }                                                                             \
} while (0)

__device__ __forceinline__ void ldsm4(uint32_t* r, uint32_t addr) {
    asm volatile("ldmatrix.sync.aligned.m8n8.x4.shared.b16 {%0,%1,%2,%3}, [%4];"
        : "=r"(r[0]), "=r"(r[1]), "=r"(r[2]), "=r"(r[3]) : "r"(addr));
}
__device__ __forceinline__ void mma16816(float* c, const uint32_t* a, uint32_t b0, uint32_t b1) {
    asm volatile("mma.sync.aligned.m16n8k16.row.col.f32.f16.f16.f32 "
        "{%0,%1,%2,%3}, {%4,%5,%6,%7}, {%8,%9}, {%0,%1,%2,%3};"
        : "+f"(c[0]), "+f"(c[1]), "+f"(c[2]), "+f"(c[3])
        : "r"(a[0]), "r"(a[1]), "r"(a[2]), "r"(a[3]), "r"(b0), "r"(b1));
}
__device__ __forceinline__ void ffma2(unsigned long long& d,
                                      unsigned long long a,
                                      unsigned long long b) {
    asm("fma.rn.f32x2 %0, %1, %2, %0;" : "+l"(d) : "l"(a), "l"(b));
}
__device__ __forceinline__ uint32_t encf(float f) {
    uint32_t u = __float_as_uint(f);
    return (u & 0x80000000u) ? ~u : (u | 0x80000000u);
}
__device__ __forceinline__ float decf(uint32_t e) {
    uint32_t u = (e & 0x80000000u) ? (e & 0x7fffffffu) : ~e;
    return __uint_as_float(u);
}
__device__ __forceinline__ uint32_t packh2(__half a, __half b) {
    __half2 h = __halves2half2(a, b);
    return *reinterpret_cast<uint32_t*>(&h);
}

// ===== launch #1: init =====
__global__ void init_kernel() {
    int i = blockIdx.x * 256 + threadIdx.x;
    g_best[i] = ~0ull;
    g_best2[i] = 0xFFFFFFFFu;
    g_isfix[i] = 0;
    g_fbest[i] = ~0ull;
    if (i == 0) g_fixcnt = 0;
}

// ===== launches #2/#3: prep =====
__global__ void prep_a_kernel(const float* __restrict__ x) {
    int t = blockIdx.x * 256 + threadIdx.x;
    int row = t >> 5, u = t & 31;
    int ks = u >> 1, kh = u & 1;
    const float* r = x + (size_t)row * CDIM + ks * 16 + kh * 8;
    float s = 0.f;
    __half h[8];
#pragma unroll
    for (int i = 0; i < 8; ++i) { float v = r[i]; s = fmaf(v, v, s); h[i] = __float2half(v); }
    uint4 val;
    val.x = packh2(h[0], h[1]); val.y = packh2(h[2], h[3]);
    val.z = packh2(h[4], h[5]); val.w = packh2(h[6], h[7]);
    int tile = row >> 7, rl = row & 127;
    int phys = (rl * 2 + kh) ^ ((rl >> 2) & 1);
    g_Aimg[(size_t)tile * 4096 + ks * 256 + phys] = val;
#pragma unroll
    for (int o = 16; o; o >>= 1) s += __shfl_xor_sync(0xffffffffu, s, o);
    if ((t & 31) == 0) g_xsq[row] = s;
}
__global__ void prep_b_kernel(const float* __restrict__ cb) {
    int t = blockIdx.x * 256 + threadIdx.x;
    int row = t >> 5, u = t & 31;
    int ks = u >> 1, kh = u & 1;
    const float* r = cb + (size_t)row * CDIM + ks * 16 + kh * 8;
    float s = 0.f;
    __half h[8];
#pragma unroll
    for (int i = 0; i < 8; ++i) { float v = r[i]; s = fmaf(v, v, s); h[i] = __float2half(v); }
    uint4 val;
    val.x = packh2(h[0], h[1]); val.y = packh2(h[2], h[3]);
    val.z = packh2(h[4], h[5]); val.w = packh2(h[6], h[7]);
    int nt = row >> 6, rl = row & 63;
    int phys = (rl * 2 + kh) ^ ((rl >> 2) & 1);
    g_Bimg[(size_t)nt * 2048 + ks * 128 + phys] = val;
#pragma unroll
    for (int o = 16; o; o >>= 1) s += __shfl_xor_sync(0xffffffffu, s, o);
    if ((t & 31) == 0) { g_cbsq[row] = s; g_cbsqo[row] = s + VOFF; }
}

// ===== launch #4: main HMMA kernel — partial A-stationary, 512 threads =====
__device__ __forceinline__ void issue_A(uint32_t smemA, int m, int tid) {
    const uint4* src = g_Aimg + (size_t)m * 4096 + tid;
#pragma unroll
    for (int i = 0; i < 8; ++i)
        cp_async16(smemA + (tid + i * 512) * 16, src + i * 512);
}
__device__ __forceinline__ void produce_stage(uint32_t smB, uint32_t bar, int jpi, int j, int tid) {
    int sp = jpi & 3;
    int par = (((jpi >> 2) & 1) ^ 1);
    MBAR_WAIT(bar + 32 + sp * 8, par);             // empty[sp]
    const uint4* src = g_Bimg + (size_t)(j & (NUM_NT - 1)) * 2048 + tid;
    uint32_t dst = smB + sp * 32768 + tid * 16;
#pragma unroll
    for (int i = 0; i < 4; ++i)
        cp_async16(dst + i * 8192, src + i * 512);
    CP_ASYNC_MBAR_ARRIVE(bar + sp * 8);            // full[sp]
}

__global__ __launch_bounds__(THREADS, 1)
void vq_hmma_kernel() {
    extern __shared__ char smem[];
    uint32_t sb = smem_u32(smem);
    uint32_t smA = sb + SMEM_A;
    uint32_t smB = sb + SMEM_B;
    uint32_t bar = sb + SMEM_BAR;

    int tid = threadIdx.x;
    int l = tid & 31, w = tid >> 5;
    int wm = w >> 1, wn = w & 1;     // wm: 8 row-slices of 16; wn: 2 col-halves of 32

    uint32_t aoff, boff[2];
    {
        int row = wm * 16 + (l & 15);
        int kh = l >> 4;
        aoff = (uint32_t)(((row * 2 + kh) ^ ((row >> 2) & 1)) << 4);
    }
#pragma unroll
    for (int g = 0; g < 2; ++g) {
        int code = wn * 32 + g * 16 + (l & 7) + ((l >> 4) << 3);
        int kh = (l >> 3) & 1;
        boff[g] = (uint32_t)(((code * 2 + kh) ^ ((code >> 2) & 1)) << 4);
    }

    int start = (int)(((long long)blockIdx.x * JOBS) / NCTA);
    int end   = (int)(((long long)(blockIdx.x + 1) * JOBS) / NCTA);
    int njobs = end - start;

    if (tid == 0) {
#pragma unroll
        for (int s = 0; s < 4; ++s) {
            MBARRIER_INIT(bar + s * 8, 512);        // full
            MBARRIER_INIT(bar + 32 + s * 8, 512);   // empty
        }
    }
    __syncthreads();

    int cur_m = start >> 7;
    issue_A(smA, cur_m, tid); CP_COMMIT();
#pragma unroll
    for (int p = 0; p < 3; ++p)
        if (p < njobs) produce_stage(smB, bar, p, start + p, tid);
    CP_WAIT(0);
    __syncthreads();

    // ---- partial A-stationary: first 8 ksteps in regs (32 regs, no spill) ----
    uint32_t areg[ASTAT][4];
#pragma unroll
    for (int ks = 0; ks < ASTAT; ++ks)
        ldsm4(areg[ks], smA + ks * 4096 + aoff);

    float rb[2] = {3.4e38f, 3.4e38f};
    float rs[2] = {3.4e38f, 3.4e38f};
    int   ri[2] = {0, 0};

    for (int ji = 0; ji < njobs; ++ji) {
        int j = start + ji;
        int ntj = j & (NUM_NT - 1);
        int s = ji & 3;

        MBAR_WAIT(bar + s * 8, (ji >> 2) & 1);      // full[s]

        float qv[8];
        int qbase = ntj * NT + wn * 32 + (l & 3) * 2;
#pragma unroll
        for (int nb = 0; nb < 4; ++nb) {
            qv[nb * 2]     = __ldg(&g_cbsqo[qbase + nb * 8]);
            qv[nb * 2 + 1] = __ldg(&g_cbsqo[qbase + nb * 8 + 1]);
        }

        float acc[4][4];
#pragma unroll
        for (int nb = 0; nb < 4; ++nb)
#pragma unroll
            for (int q = 0; q < 4; ++q) acc[nb][q] = 0.f;

        uint32_t Bstage = smB + s * 32768;
#pragma unroll
        for (int ks = 0; ks < KSTEPS; ++ks) {
            uint32_t Bpan = Bstage + ks * 2048;
            uint32_t bf[2][4];
            ldsm4(bf[0], Bpan + boff[0]);
            ldsm4(bf[1], Bpan + boff[1]);
            uint32_t af[4];
            const uint32_t* ap;
            if (ks < ASTAT) {
                ap = areg[ks];
            } else {
                ldsm4(af, smA + ks * 4096 + aoff);
                ap = af;
            }
#pragma unroll
            for (int g = 0; g < 2; ++g) {
                mma16816(acc[g*2  ], ap, bf[g][0], bf[g][1]);
                mma16816(acc[g*2+1], ap, bf[g][2], bf[g][3]);
            }
        }

        MBARRIER_ARRIVE(bar + 32 + s * 8);          // empty[s]

        // epilogue (registers only)
#pragma unroll
        for (int h = 0; h < 2; ++h) {
            uint32_t k1 = 0xFFFFFFFFu, k2 = 0xFFFFFFFFu;
#pragma unroll
            for (int nb = 0; nb < 4; ++nb)
#pragma unroll
                for (int c = 0; c < 2; ++c) {
                    float v = fmaf(-2.f, acc[nb][h * 2 + c], qv[nb * 2 + c]);
                    uint32_t k = (__float_as_uint(v) & 0xFFFFFFF8u) | (uint32_t)(nb * 2 + c);
                    uint32_t t = max(k1, k);
                    k1 = min(k1, k);
                    k2 = min(k2, t);
                }
            float v1 = __uint_as_float(k1 & 0xFFFFFFF8u);
            float v2 = __uint_as_float(k2 & 0xFFFFFFF8u);
            int li = (int)(k1 & 7u);
            int gidx = qbase + (li >> 1) * 8 + (li & 1);
            if (v1 < rb[h]) {
                rs[h] = fminf(rb[h], v2);
                rb[h] = v1; ri[h] = gidx;
            } else {
                rs[h] = fminf(rs[h], v1);
            }
        }

        int jn = j + 1;
        bool m_change = (jn < end) && ((jn >> 7) != cur_m);
        if (m_change || jn == end) {
#pragma unroll
            for (int h = 0; h < 2; ++h) {
                float bv = rb[h], sv = rs[h];
                int bi = ri[h];
#pragma unroll
                for (int o = 1; o < 4; o <<= 1) {
                    float ov = __shfl_xor_sync(0xffffffffu, bv, o);
                    int   oi = __shfl_xor_sync(0xffffffffu, bi, o);
                    float os = __shfl_xor_sync(0xffffffffu, sv, o);
                    if (ov < bv || (ov == bv && oi < bi)) {
                        sv = fminf(bv, os); bv = ov; bi = oi;
                    } else {
                        sv = fminf(sv, ov);
                    }
                }
                if ((l & 3) == 0) {
                    int r = cur_m * MT + wm * 16 + h * 8 + (l >> 2);
                    unsigned long long key =
                        ((unsigned long long)encf(bv) << 32) | (uint32_t)bi;
                    unsigned long long old = atomicMin(&g_best[r], key);
                    uint32_t oldenc = (uint32_t)(old >> 32);
                    uint32_t be = encf(bv);
                    uint32_t cand = min(encf(sv), max(be, oldenc));
                    atomicMin(&g_best2[r], cand);
                }
                rb[h] = 3.4e38f; rs[h] = 3.4e38f; ri[h] = 0;
            }
        }

        if (ji + 3 < njobs) produce_stage(smB, bar, ji + 3, start + ji + 3, tid);

        if (m_change) {
            cur_m = jn >> 7;
            __syncthreads();                        // all warps done reading smA
            issue_A(smA, cur_m, tid); CP_COMMIT();
            CP_WAIT(0);
            __syncthreads();                        // new A visible
#pragma unroll
            for (int ks = 0; ks < ASTAT; ++ks)      // refill stationary A regs
                ldsm4(areg[ks], smA + ks * 4096 + aoff);
        }
    }
}

// ===== launch #5: finalize, flag close rows =====
__global__ void final_kernel(float* __restrict__ out) {
    int i = blockIdx.x * 256 + threadIdx.x;
    unsigned long long key = g_best[i];
    int idx = (int)(uint32_t)key;
    float val = decf((uint32_t)(key >> 32)) - VOFF;
    float sec = decf(g_best2[i]) - VOFF;
    out[IDX_OFF + i]  = (float)idx;
    out[DIST_OFF + i] = g_xsq[i] + val;
    g_idx[i] = idx;
    if (sec - val < MARGIN) {
        g_isfix[i] = 1;
        int p = atomicAdd(&g_fixcnt, 1);
        g_fixrows[p] = i;
    }
}

// ===== launch #6: exact fp32 rescan, K-sliced 8-way, packed f32x2 FMA =====
__global__ __launch_bounds__(256) void fixup_kernel(const float* __restrict__ x,
                                                    const float* __restrict__ cb) {
    __shared__ float4 xs[FIXROWS][64];
    __shared__ unsigned long long wk[FIXROWS][2];
    int tid = threadIdx.x;
    int n = g_fixcnt;
    int ngroups = (n + FIXROWS - 1) / FIXROWS;
    int slice = blockIdx.x & (KSLICES - 1);
    int g0 = blockIdx.x >> 3;
    const ulonglong2* cu = reinterpret_cast<const ulonglong2*>(cb);
    for (int g = g0; g < ngroups; g += NCTA) {
        __syncthreads();
        for (int i = tid; i < FIXROWS * 64; i += 256) {
            int r = i >> 6, q = i & 63;
            int fr = g * FIXROWS + r;
            int row = g_fixrows[(fr < n) ? fr : g * FIXROWS];
            xs[r][q] = reinterpret_cast<const float4*>(x)[(size_t)row * 64 + q];
        }
        __syncthreads();
        int rg = tid >> 6;
        int cg = tid & 63;
        float bv[4] = {3.4e38f,3.4e38f,3.4e38f,3.4e38f};
        int   bi[4] = {0,0,0,0};
        for (int k = slice * 4; k < slice * 4 + 4; ++k) {
            int c0 = k * 256 + cg * 4;
            unsigned long long acc2[4][4];
#pragma unroll
            for (int r = 0; r < 4; ++r)
#pragma unroll
                for (int cc = 0; cc < 4; ++cc) acc2[r][cc] = 0ull;
#pragma unroll 8
            for (int q = 0; q < 64; ++q) {
                ulonglong2 xv[4];
#pragma unroll
                for (int r = 0; r < 4; ++r)
                    xv[r] = *reinterpret_cast<const ulonglong2*>(&xs[rg * 4 + r][q]);
#pragma unroll
                for (int cc = 0; cc < 4; ++cc) {
                    ulonglong2 v = cu[(size_t)(c0 + cc) * 64 + q];
#pragma unroll
                    for (int r = 0; r < 4; ++r) {
                        ffma2(acc2[r][cc], xv[r].x, v.x);
                        ffma2(acc2[r][cc], xv[r].y, v.y);
                    }
                }
            }
#pragma unroll
            for (int cc = 0; cc < 4; ++cc) {
                float cq = __ldg(&g_cbsq[c0 + cc]);
#pragma unroll
                for (int r = 0; r < 4; ++r) {
                    float lo, hi;
                    asm("mov.b64 {%0,%1}, %2;" : "=f"(lo), "=f"(hi) : "l"(acc2[r][cc]));
                    float val = fmaf(-2.f, lo + hi, cq);
                    if (val < bv[r] || (val == bv[r] && c0 + cc < bi[r])) {
                        bv[r] = val; bi[r] = c0 + cc;
                    }
                }
            }
        }
#pragma unroll
        for (int r = 0; r < 4; ++r) {
            unsigned long long key =
                ((unsigned long long)encf(bv[r]) << 32) | (uint32_t)bi[r];
#pragma unroll
            for (int o = 16; o; o >>= 1) {
                unsigned long long ok = __shfl_xor_sync(0xffffffffu, key, o);
                key = min(key, ok);
            }
            if ((tid & 31) == 0) wk[rg * 4 + r][(tid >> 5) & 1] = key;
        }
        __syncthreads();
        if (tid < FIXROWS) {
            int fr = g * FIXROWS + tid;
            if (fr < n) {
                unsigned long long best = min(wk[tid][0], wk[tid][1]);
                atomicMin(&g_fbest[g_fixrows[fr]], best);
            }
        }
    }
}

// ===== launch #7: apply fixups + gather codes =====
__global__ void gather_kernel(const float* __restrict__ cb, float* __restrict__ out) {
    __shared__ int s_idx[4];
    int tid = threadIdx.x;
    int rslot = tid >> 6;
    int row = blockIdx.x * 4 + rslot;
    int c = tid & 63;
    if (c == 0) {
        int idx;
        if (g_isfix[row]) {
            unsigned long long best = g_fbest[row];
            idx = (int)(uint32_t)best;
            out[IDX_OFF + row]  = (float)idx;
            out[DIST_OFF + row] = g_xsq[row] + decf((uint32_t)(best >> 32));
        } else {
            idx = g_idx[row];
        }
        s_idx[rslot] = idx;
    }
    __syncthreads();
    int idx = s_idx[rslot];
    reinterpret_cast<float4*>(out)[(size_t)row * 64 + c] =
        reinterpret_cast<const float4*>(cb)[(size_t)idx * 64 + c];
}

extern "C" void kernel_launch(void* const* d_in, const int* in_sizes, int n_in,
                              void* d_out, int out_size) {
    const float* x  = (const float*)d_in[0];   // z_e_x  [8,4096,256] f32
    const float* cb = (const float*)d_in[1];   // codebook [8192,256] f32
    float* out = (float*)d_out;                // codes | idx | distances (f32)

    cudaFuncSetAttribute(vq_hmma_kernel,
                         cudaFuncAttributeMaxDynamicSharedMemorySize, SMEM_TOTAL);

    init_kernel<<<RTOT / 256, 256>>>();                    // #1
    prep_a_kernel<<<(RTOT * 32) / 256, 256>>>(x);          // #2
    prep_b_kernel<<<(KTOT * 32) / 256, 256>>>(cb);         // #3
    vq_hmma_kernel<<<NCTA, THREADS, SMEM_TOTAL>>>();       // #4  <- ncu capture slot
    final_kernel<<<RTOT / 256, 256>>>(out);                // #5
    fixup_kernel<<<NCTA * KSLICES, 256>>>(x, cb);          // #6
    gather_kernel<<<RTOT / 4, 256>>>(cb, out);             // #7
}

// round 16
// speedup vs baseline: 1.1595x; 1.1164x over previous
#include <cuda_runtime.h>
#include <cuda_fp16.h>
#include <cstdint>

// ===== problem constants =====
#define RTOT  32768
#define CDIM  256
#define KTOT  8192
#define MT    128
#define NT    64               // 32KB B stages
#define KSTEPS 16
#define ASTAT 8                // ksteps held stationary in registers
#define NUM_MT (RTOT/MT)       // 256
#define NUM_NT (KTOT/NT)       // 128
#define JOBS  (NUM_MT*NUM_NT)  // 32768
#define NCTA  148
#define THREADS 512            // 16 warps, 4 per SMSP

#define SMEM_A    0
#define SMEM_B    65536        // 4 stages x 32KB
#define SMEM_BAR  196608
#define SMEM_TOTAL 196736

#define IDX_OFF  8388608
#define DIST_OFF (8388608+32768)

#define VOFF 1024.0f
#define MARGIN 0.09f
#define FIXROWS 16
#define KSLICES 16

// ===== device globals (static scratch) =====
__device__ uint4 g_Aimg[(size_t)NUM_MT*4096];
__device__ uint4 g_Bimg[(size_t)NUM_NT*2048];
__device__ float g_cbsq[KTOT];
__device__ float g_cbsqo[KTOT];
__device__ float g_xsq[RTOT];
__device__ int   g_idx[RTOT];
__device__ unsigned long long g_best[RTOT];
__device__ unsigned int g_best2[RTOT];
__device__ int g_fixcnt;
__device__ int g_fixrows[RTOT];
__device__ int g_isfix[RTOT];
__device__ unsigned long long g_fbest[RTOT];

// ===== helpers =====
__device__ __forceinline__ uint32_t smem_u32(const void* p) {
    uint32_t a;
    asm("{ .reg .u64 t; cvta.to.shared.u64 t, %1; cvt.u32.u64 %0, t; }" : "=r"(a) : "l"(p));
    return a;
}
__device__ __forceinline__ void cp_async16(uint32_t sa, const void* g) {
    asm volatile("cp.async.cg.shared.global [%0], [%1], 16;" :: "r"(sa), "l"(g));
}
#define CP_COMMIT() asm volatile("cp.async.commit_group;" ::: "memory")
#define CP_WAIT(N)  asm volatile("cp.async.wait_group %0;" :: "n"(N) : "memory")

#define MBARRIER_INIT(mb, c) asm volatile("mbarrier.init.shared.b64 [%0], %1;" :: "r"((uint32_t)(mb)), "r"((uint32_t)(c)) : "memory")
#define MBARRIER_ARRIVE(mb)  asm volatile("mbarrier.arrive.shared.b64 _, [%0];" :: "r"((uint32_t)(mb)) : "memory")
#define CP_ASYNC_MBAR_ARRIVE(mb) asm volatile("cp.async.mbarrier.arrive.noinc.shared.b64 [%0];" :: "r"((uint32_t)(mb)) : "memory")

#define MBAR_WAIT(mb, par) do {                                                   \
    uint32_t _m = (uint32_t)(mb), _p = (uint32_t)(par), _d;                       \
    asm volatile("{\n\t.reg .pred p;\n\t"                                         \
        "mbarrier.try_wait.parity.acquire.cta.shared::cta.b64 p, [%1], %2;\n\t"   \
        "selp.b32 %0,1,0,p;\n\t}" : "=r"(_d) : "r"(_m), "r"(_p) : "memory");      \
    if (!_d) {                                                                    \
        asm volatile("{\n\t.reg .pred P1;\n\t"                                    \
        "WL_%=:\n\t"                                                              \
        "mbarrier.try_wait.parity.acquire.cta.shared::cta.b64 P1, [%0], %1, 0x989680;\n\t" \
        "@P1 bra.uni WD_%=;\n\t"                                                  \
        "bra.uni WL_%=;\n\t"                                                      \
        "WD_%=:\n\t}" :: "r"(_m), "r"(_p) : "memory");                            \
    }                                                                             \
} while (0)

__device__ __forceinline__ void ldsm4(uint32_t* r, uint32_t addr) {
    asm volatile("ldmatrix.sync.aligned.m8n8.x4.shared.b16 {%0,%1,%2,%3}, [%4];"
        : "=r"(r[0]), "=r"(r[1]), "=r"(r[2]), "=r"(r[3]) : "r"(addr));
}
__device__ __forceinline__ void mma16816(float* c, const uint32_t* a, uint32_t b0, uint32_t b1) {
    asm volatile("mma.sync.aligned.m16n8k16.row.col.f32.f16.f16.f32 "
        "{%0,%1,%2,%3}, {%4,%5,%6,%7}, {%8,%9}, {%0,%1,%2,%3};"
        : "+f"(c[0]), "+f"(c[1]), "+f"(c[2]), "+f"(c[3])
        : "r"(a[0]), "r"(a[1]), "r"(a[2]), "r"(a[3]), "r"(b0), "r"(b1));
}
__device__ __forceinline__ void ffma2(unsigned long long& d,
                                      unsigned long long a,
                                      unsigned long long b) {
    asm("fma.rn.f32x2 %0, %1, %2, %0;" : "+l"(d) : "l"(a), "l"(b));
}
__device__ __forceinline__ uint32_t encf(float f) {
    uint32_t u = __float_as_uint(f);
    return (u & 0x80000000u) ? ~u : (u | 0x80000000u);
}
__device__ __forceinline__ float decf(uint32_t e) {
    uint32_t u = (e & 0x80000000u) ? (e & 0x7fffffffu) : ~e;
    return __uint_as_float(u);
}
__device__ __forceinline__ uint32_t packh2(__half a, __half b) {
    __half2 h = __halves2half2(a, b);
    return *reinterpret_cast<uint32_t*>(&h);
}

// ===== launch #1: fused init + prep A + prep B =====
// blocks [0,4096): A image (+ best/second/flag init on blocks [0,128))
// blocks [4096,5120): B image
__global__ void prep_kernel(const float* __restrict__ x, const float* __restrict__ cb) {
    int b = blockIdx.x;
    int gt = b * 256 + threadIdx.x;

    if (gt < RTOT) {                 // init arrays (first 128 blocks)
        g_best[gt] = ~0ull;
        g_best2[gt] = 0xFFFFFFFFu;
        g_isfix[gt] = 0;
        g_fbest[gt] = ~0ull;
        if (gt == 0) g_fixcnt = 0;
    }

    if (b < 4096) {
        int t = gt;                  // A: rows 0..32767, 32 threads/row
        int row = t >> 5, u = t & 31;
        int ks = u >> 1, kh = u & 1;
        const float* r = x + (size_t)row * CDIM + ks * 16 + kh * 8;
        float s = 0.f;
        __half h[8];
#pragma unroll
        for (int i = 0; i < 8; ++i) { float v = r[i]; s = fmaf(v, v, s); h[i] = __float2half(v); }
        uint4 val;
        val.x = packh2(h[0], h[1]); val.y = packh2(h[2], h[3]);
        val.z = packh2(h[4], h[5]); val.w = packh2(h[6], h[7]);
        int tile = row >> 7, rl = row & 127;
        int phys = (rl * 2 + kh) ^ ((rl >> 2) & 1);
        g_Aimg[(size_t)tile * 4096 + ks * 256 + phys] = val;
#pragma unroll
        for (int o = 16; o; o >>= 1) s += __shfl_xor_sync(0xffffffffu, s, o);
        if ((t & 31) == 0) g_xsq[row] = s;
    } else {
        int t = gt - 4096 * 256;     // B: rows 0..8191
        int row = t >> 5, u = t & 31;
        int ks = u >> 1, kh = u & 1;
        const float* r = cb + (size_t)row * CDIM + ks * 16 + kh * 8;
        float s = 0.f;
        __half h[8];
#pragma unroll
        for (int i = 0; i < 8; ++i) { float v = r[i]; s = fmaf(v, v, s); h[i] = __float2half(v); }
        uint4 val;
        val.x = packh2(h[0], h[1]); val.y = packh2(h[2], h[3]);
        val.z = packh2(h[4], h[5]); val.w = packh2(h[6], h[7]);
        int nt = row >> 6, rl = row & 63;
        int phys = (rl * 2 + kh) ^ ((rl >> 2) & 1);
        g_Bimg[(size_t)nt * 2048 + ks * 128 + phys] = val;
#pragma unroll
        for (int o = 16; o; o >>= 1) s += __shfl_xor_sync(0xffffffffu, s, o);
        if ((t & 31) == 0) { g_cbsq[row] = s; g_cbsqo[row] = s + VOFF; }
    }
}

// ===== launch #2: main HMMA kernel — partial A-stationary, 512 threads =====
__device__ __forceinline__ void issue_A(uint32_t smemA, int m, int tid) {
    const uint4* src = g_Aimg + (size_t)m * 4096 + tid;
#pragma unroll
    for (int i = 0; i < 8; ++i)
        cp_async16(smemA + (tid + i * 512) * 16, src + i * 512);
}
__device__ __forceinline__ void produce_stage(uint32_t smB, uint32_t bar, int jpi, int j, int tid) {
    int sp = jpi & 3;
    int par = (((jpi >> 2) & 1) ^ 1);
    MBAR_WAIT(bar + 32 + sp * 8, par);             // empty[sp]
    const uint4* src = g_Bimg + (size_t)(j & (NUM_NT - 1)) * 2048 + tid;
    uint32_t dst = smB + sp * 32768 + tid * 16;
#pragma unroll
    for (int i = 0; i < 4; ++i)
        cp_async16(dst + i * 8192, src + i * 512);
    CP_ASYNC_MBAR_ARRIVE(bar + sp * 8);            // full[sp]
}

__global__ __launch_bounds__(THREADS, 1)
void vq_hmma_kernel() {
    extern __shared__ char smem[];
    uint32_t sb = smem_u32(smem);
    uint32_t smA = sb + SMEM_A;
    uint32_t smB = sb + SMEM_B;
    uint32_t bar = sb + SMEM_BAR;

    int tid = threadIdx.x;
    int l = tid & 31, w = tid >> 5;
    int wm = w >> 1, wn = w & 1;     // wm: 8 row-slices of 16; wn: 2 col-halves of 32

    uint32_t aoff, boff[2];
    {
        int row = wm * 16 + (l & 15);
        int kh = l >> 4;
        aoff = (uint32_t)(((row * 2 + kh) ^ ((row >> 2) & 1)) << 4);
    }
#pragma unroll
    for (int g = 0; g < 2; ++g) {
        int code = wn * 32 + g * 16 + (l & 7) + ((l >> 4) << 3);
        int kh = (l >> 3) & 1;
        boff[g] = (uint32_t)(((code * 2 + kh) ^ ((code >> 2) & 1)) << 4);
    }

    int start = (int)(((long long)blockIdx.x * JOBS) / NCTA);
    int end   = (int)(((long long)(blockIdx.x + 1) * JOBS) / NCTA);
    int njobs = end - start;

    if (tid == 0) {
#pragma unroll
        for (int s = 0; s < 4; ++s) {
            MBARRIER_INIT(bar + s * 8, 512);        // full
            MBARRIER_INIT(bar + 32 + s * 8, 512);   // empty
        }
    }
    __syncthreads();

    int cur_m = start >> 7;
    issue_A(smA, cur_m, tid); CP_COMMIT();
#pragma unroll
    for (int p = 0; p < 3; ++p)
        if (p < njobs) produce_stage(smB, bar, p, start + p, tid);
    CP_WAIT(0);
    __syncthreads();

    // ---- partial A-stationary: first 8 ksteps in regs (32 regs, no spill) ----
    uint32_t areg[ASTAT][4];
#pragma unroll
    for (int ks = 0; ks < ASTAT; ++ks)
        ldsm4(areg[ks], smA + ks * 4096 + aoff);

    float rb[2] = {3.4e38f, 3.4e38f};
    float rs[2] = {3.4e38f, 3.4e38f};
    int   ri[2] = {0, 0};

    for (int ji = 0; ji < njobs; ++ji) {
        int j = start + ji;
        int ntj = j & (NUM_NT - 1);
        int s = ji & 3;

        MBAR_WAIT(bar + s * 8, (ji >> 2) & 1);      // full[s]

        float qv[8];
        int qbase = ntj * NT + wn * 32 + (l & 3) * 2;
#pragma unroll
        for (int nb = 0; nb < 4; ++nb) {
            qv[nb * 2]     = __ldg(&g_cbsqo[qbase + nb * 8]);
            qv[nb * 2 + 1] = __ldg(&g_cbsqo[qbase + nb * 8 + 1]);
        }

        float acc[4][4];
#pragma unroll
        for (int nb = 0; nb < 4; ++nb)
#pragma unroll
            for (int q = 0; q < 4; ++q) acc[nb][q] = 0.f;

        uint32_t Bstage = smB + s * 32768;
#pragma unroll
        for (int ks = 0; ks < KSTEPS; ++ks) {
            uint32_t Bpan = Bstage + ks * 2048;
            uint32_t bf[2][4];
            ldsm4(bf[0], Bpan + boff[0]);
            ldsm4(bf[1], Bpan + boff[1]);
            uint32_t af[4];
            const uint32_t* ap;
            if (ks < ASTAT) {
                ap = areg[ks];
            } else {
                ldsm4(af, smA + ks * 4096 + aoff);
                ap = af;
            }
#pragma unroll
            for (int g = 0; g < 2; ++g) {
                mma16816(acc[g*2  ], ap, bf[g][0], bf[g][1]);
                mma16816(acc[g*2+1], ap, bf[g][2], bf[g][3]);
            }
        }

        MBARRIER_ARRIVE(bar + 32 + s * 8);          // empty[s]

        // epilogue (registers only)
#pragma unroll
        for (int h = 0; h < 2; ++h) {
            uint32_t k1 = 0xFFFFFFFFu, k2 = 0xFFFFFFFFu;
#pragma unroll
            for (int nb = 0; nb < 4; ++nb)
#pragma unroll
                for (int c = 0; c < 2; ++c) {
                    float v = fmaf(-2.f, acc[nb][h * 2 + c], qv[nb * 2 + c]);
                    uint32_t k = (__float_as_uint(v) & 0xFFFFFFF8u) | (uint32_t)(nb * 2 + c);
                    uint32_t t = max(k1, k);
                    k1 = min(k1, k);
                    k2 = min(k2, t);
                }
            float v1 = __uint_as_float(k1 & 0xFFFFFFF8u);
            float v2 = __uint_as_float(k2 & 0xFFFFFFF8u);
            int li = (int)(k1 & 7u);
            int gidx = qbase + (li >> 1) * 8 + (li & 1);
            if (v1 < rb[h]) {
                rs[h] = fminf(rb[h], v2);
                rb[h] = v1; ri[h] = gidx;
            } else {
                rs[h] = fminf(rs[h], v1);
            }
        }

        int jn = j + 1;
        bool m_change = (jn < end) && ((jn >> 7) != cur_m);
        if (m_change || jn == end) {
#pragma unroll
            for (int h = 0; h < 2; ++h) {
                float bv = rb[h], sv = rs[h];
                int bi = ri[h];
#pragma unroll
                for (int o = 1; o < 4; o <<= 1) {
                    float ov = __shfl_xor_sync(0xffffffffu, bv, o);
                    int   oi = __shfl_xor_sync(0xffffffffu, bi, o);
                    float os = __shfl_xor_sync(0xffffffffu, sv, o);
                    if (ov < bv || (ov == bv && oi < bi)) {
                        sv = fminf(bv, os); bv = ov; bi = oi;
                    } else {
                        sv = fminf(sv, ov);
                    }
                }
                if ((l & 3) == 0) {
                    int r = cur_m * MT + wm * 16 + h * 8 + (l >> 2);
                    unsigned long long key =
                        ((unsigned long long)encf(bv) << 32) | (uint32_t)bi;
                    unsigned long long old = atomicMin(&g_best[r], key);
                    uint32_t oldenc = (uint32_t)(old >> 32);
                    uint32_t be = encf(bv);
                    uint32_t cand = min(encf(sv), max(be, oldenc));
                    atomicMin(&g_best2[r], cand);
                }
                rb[h] = 3.4e38f; rs[h] = 3.4e38f; ri[h] = 0;
            }
        }

        if (ji + 3 < njobs) produce_stage(smB, bar, ji + 3, start + ji + 3, tid);

        if (m_change) {
            cur_m = jn >> 7;
            __syncthreads();                        // all warps done reading smA
            issue_A(smA, cur_m, tid); CP_COMMIT();
            CP_WAIT(0);
            __syncthreads();                        // new A visible
#pragma unroll
            for (int ks = 0; ks < ASTAT; ++ks)      // refill stationary A regs
                ldsm4(areg[ks], smA + ks * 4096 + aoff);
        }
    }
}

// ===== launch #3: finalize, flag close rows =====
__global__ void final_kernel(float* __restrict__ out) {
    int i = blockIdx.x * 256 + threadIdx.x;
    unsigned long long key = g_best[i];
    int idx = (int)(uint32_t)key;
    float val = decf((uint32_t)(key >> 32)) - VOFF;
    float sec = decf(g_best2[i]) - VOFF;
    out[IDX_OFF + i]  = (float)idx;
    out[DIST_OFF + i] = g_xsq[i] + val;
    g_idx[i] = idx;
    if (sec - val < MARGIN) {
        g_isfix[i] = 1;
        int p = atomicAdd(&g_fixcnt, 1);
        g_fixrows[p] = i;
    }
}

// ===== launch #4: exact fp32 rescan, K-sliced 16-way, packed f32x2 FMA =====
__global__ __launch_bounds__(256) void fixup_kernel(const float* __restrict__ x,
                                                    const float* __restrict__ cb) {
    __shared__ float4 xs[FIXROWS][64];
    __shared__ unsigned long long wk[FIXROWS][2];
    int tid = threadIdx.x;
    int n = g_fixcnt;
    int ngroups = (n + FIXROWS - 1) / FIXROWS;
    int slice = blockIdx.x & (KSLICES - 1);     // 512-code slice
    int g0 = blockIdx.x >> 4;
    const ulonglong2* cu = reinterpret_cast<const ulonglong2*>(cb);
    for (int g = g0; g < ngroups; g += NCTA) {
        __syncthreads();
        for (int i = tid; i < FIXROWS * 64; i += 256) {
            int r = i >> 6, q = i & 63;
            int fr = g * FIXROWS + r;
            int row = g_fixrows[(fr < n) ? fr : g * FIXROWS];
            xs[r][q] = reinterpret_cast<const float4*>(x)[(size_t)row * 64 + q];
        }
        __syncthreads();
        int rg = tid >> 6;
        int cg = tid & 63;
        float bv[4] = {3.4e38f,3.4e38f,3.4e38f,3.4e38f};
        int   bi[4] = {0,0,0,0};
        for (int k = slice * 2; k < slice * 2 + 2; ++k) {
            int c0 = k * 256 + cg * 4;
            unsigned long long acc2[4][4];
#pragma unroll
            for (int r = 0; r < 4; ++r)
#pragma unroll
                for (int cc = 0; cc < 4; ++cc) acc2[r][cc] = 0ull;
#pragma unroll 8
            for (int q = 0; q < 64; ++q) {
                ulonglong2 xv[4];
#pragma unroll
                for (int r = 0; r < 4; ++r)
                    xv[r] = *reinterpret_cast<const ulonglong2*>(&xs[rg * 4 + r][q]);
#pragma unroll
                for (int cc = 0; cc < 4; ++cc) {
                    ulonglong2 v = cu[(size_t)(c0 + cc) * 64 + q];
#pragma unroll
                    for (int r = 0; r < 4; ++r) {
                        ffma2(acc2[r][cc], xv[r].x, v.x);
                        ffma2(acc2[r][cc], xv[r].y, v.y);
                    }
                }
            }
#pragma unroll
            for (int cc = 0; cc < 4; ++cc) {
                float cq = __ldg(&g_cbsq[c0 + cc]);
#pragma unroll
                for (int r = 0; r < 4; ++r) {
                    float lo, hi;
                    asm("mov.b64 {%0,%1}, %2;" : "=f"(lo), "=f"(hi) : "l"(acc2[r][cc]));
                    float val = fmaf(-2.f, lo + hi, cq);
                    if (val < bv[r] || (val == bv[r] && c0 + cc < bi[r])) {
                        bv[r] = val; bi[r] = c0 + cc;
                    }
                }
            }
        }
#pragma unroll
        for (int r = 0; r < 4; ++r) {
            unsigned long long key =
                ((unsigned long long)encf(bv[r]) << 32) | (uint32_t)bi[r];
#pragma unroll
            for (int o = 16; o; o >>= 1) {
                unsigned long long ok = __shfl_xor_sync(0xffffffffu, key, o);
                key = min(key, ok);
            }
            if ((tid & 31) == 0) wk[rg * 4 + r][(tid >> 5) & 1] = key;
        }
        __syncthreads();
        if (tid < FIXROWS) {
            int fr = g * FIXROWS + tid;
            if (fr < n) {
                unsigned long long best = min(wk[tid][0], wk[tid][1]);
                atomicMin(&g_fbest[g_fixrows[fr]], best);
            }
        }
    }
}

// ===== launch #5: apply fixups + gather codes =====
__global__ void gather_kernel(const float* __restrict__ cb, float* __restrict__ out) {
    __shared__ int s_idx[4];
    int tid = threadIdx.x;
    int rslot = tid >> 6;
    int row = blockIdx.x * 4 + rslot;
    int c = tid & 63;
    if (c == 0) {
        int idx;
        if (g_isfix[row]) {
            unsigned long long best = g_fbest[row];
            idx = (int)(uint32_t)best;
            out[IDX_OFF + row]  = (float)idx;
            out[DIST_OFF + row] = g_xsq[row] + decf((uint32_t)(best >> 32));
        } else {
            idx = g_idx[row];
        }
        s_idx[rslot] = idx;
    }
    __syncthreads();
    int idx = s_idx[rslot];
    reinterpret_cast<float4*>(out)[(size_t)row * 64 + c] =
        reinterpret_cast<const float4*>(cb)[(size_t)idx * 64 + c];
}

extern "C" void kernel_launch(void* const* d_in, const int* in_sizes, int n_in,
                              void* d_out, int out_size) {
    const float* x  = (const float*)d_in[0];   // z_e_x  [8,4096,256] f32
    const float* cb = (const float*)d_in[1];   // codebook [8192,256] f32
    float* out = (float*)d_out;                // codes | idx | distances (f32)

    cudaFuncSetAttribute(vq_hmma_kernel,
                         cudaFuncAttributeMaxDynamicSharedMemorySize, SMEM_TOTAL);

    prep_kernel<<<5120, 256>>>(x, cb);                     // #1 (init + prep A + prep B)
    vq_hmma_kernel<<<NCTA, THREADS, SMEM_TOTAL>>>();       // #2
    final_kernel<<<RTOT / 256, 256>>>(out);                // #3
    fixup_kernel<<<NCTA * KSLICES, 256>>>(x, cb);          // #4  <- ncu capture slot
    gather_kernel<<<RTOT / 4, 256>>>(cb, out);             // #5
}

// round 17
// speedup vs baseline: 1.3398x; 1.1555x over previous
#include <cuda_runtime.h>
#include <cuda_fp16.h>
#include <cstdint>

// ===== problem constants =====
#define RTOT  32768
#define CDIM  256
#define KTOT  8192
#define MT    128
#define NT    64               // 32KB B stages
#define KSTEPS 16
#define ASTAT 8                // ksteps held stationary in registers
#define NUM_MT (RTOT/MT)       // 256
#define NUM_NT (KTOT/NT)       // 128
#define JOBS  (NUM_MT*NUM_NT)  // 32768
#define NCTA  148
#define THREADS 512            // 16 warps, 4 per SMSP

#define SMEM_A    0
#define SMEM_B    65536        // 4 stages x 32KB
#define SMEM_BAR  196608
#define SMEM_TOTAL 196736

#define IDX_OFF  8388608
#define DIST_OFF (8388608+32768)

#define VOFF 1024.0f
#define MARGIN 0.09f
#define FIXROWS 32
#define KSLICES 16

// ===== device globals (static scratch) =====
__device__ uint4 g_Aimg[(size_t)NUM_MT*4096];
__device__ uint4 g_Bimg[(size_t)NUM_NT*2048];
__device__ unsigned long long g_cbPu[(size_t)128*KTOT];  // pair-transposed codebook (8MB)
__device__ float g_cbsq[KTOT];
__device__ float g_cbsqo[KTOT];
__device__ float g_xsq[RTOT];
__device__ int   g_idx[RTOT];
__device__ unsigned long long g_best[RTOT];
__device__ unsigned int g_best2[RTOT];
__device__ int g_fixcnt;
__device__ int g_fixrows[RTOT];
__device__ int g_isfix[RTOT];
__device__ unsigned long long g_fbest[RTOT];

// ===== helpers =====
__device__ __forceinline__ uint32_t smem_u32(const void* p) {
    uint32_t a;
    asm("{ .reg .u64 t; cvta.to.shared.u64 t, %1; cvt.u32.u64 %0, t; }" : "=r"(a) : "l"(p));
    return a;
}
__device__ __forceinline__ void cp_async16(uint32_t sa, const void* g) {
    asm volatile("cp.async.cg.shared.global [%0], [%1], 16;" :: "r"(sa), "l"(g));
}
#define CP_COMMIT() asm volatile("cp.async.commit_group;" ::: "memory")
#define CP_WAIT(N)  asm volatile("cp.async.wait_group %0;" :: "n"(N) : "memory")

#define MBARRIER_INIT(mb, c) asm volatile("mbarrier.init.shared.b64 [%0], %1;" :: "r"((uint32_t)(mb)), "r"((uint32_t)(c)) : "memory")
#define MBARRIER_ARRIVE(mb)  asm volatile("mbarrier.arrive.shared.b64 _, [%0];" :: "r"((uint32_t)(mb)) : "memory")
#define CP_ASYNC_MBAR_ARRIVE(mb) asm volatile("cp.async.mbarrier.arrive.noinc.shared.b64 [%0];" :: "r"((uint32_t)(mb)) : "memory")

#define MBAR_WAIT(mb, par) do {                                                   \
    uint32_t _m = (uint32_t)(mb), _p = (uint32_t)(par), _d;                       \
    asm volatile("{\n\t.reg .pred p;\n\t"                                         \
        "mbarrier.try_wait.parity.acquire.cta.shared::cta.b64 p, [%1], %2;\n\t"   \
        "selp.b32 %0,1,0,p;\n\t}" : "=r"(_d) : "r"(_m), "r"(_p) : "memory");      \
    if (!_d) {                                                                    \
        asm volatile("{\n\t.reg .pred P1;\n\t"                                    \
        "WL_%=:\n\t"                                                              \
        "mbarrier.try_wait.parity.acquire.cta.shared::cta.b64 P1, [%0], %1, 0x989680;\n\t" \
        "@P1 bra.uni WD_%=;\n\t"                                                  \
        "bra.uni WL_%=;\n\t"                                                      \
        "WD_%=:\n\t}" :: "r"(_m), "r"(_p) : "memory");                            \
    }                                                                             \
} while (0)

__device__ __forceinline__ void ldsm4(uint32_t* r, uint32_t addr) {
    asm volatile("ldmatrix.sync.aligned.m8n8.x4.shared.b16 {%0,%1,%2,%3}, [%4];"
        : "=r"(r[0]), "=r"(r[1]), "=r"(r[2]), "=r"(r[3]) : "r"(addr));
}
__device__ __forceinline__ void mma16816(float* c, const uint32_t* a, uint32_t b0, uint32_t b1) {
    asm volatile("mma.sync.aligned.m16n8k16.row.col.f32.f16.f16.f32 "
        "{%0,%1,%2,%3}, {%4,%5,%6,%7}, {%8,%9}, {%0,%1,%2,%3};"
        : "+f"(c[0]), "+f"(c[1]), "+f"(c[2]), "+f"(c[3])
        : "r"(a[0]), "r"(a[1]), "r"(a[2]), "r"(a[3]), "r"(b0), "r"(b1));
}
__device__ __forceinline__ void ffma2(unsigned long long& d,
                                      unsigned long long a,
                                      unsigned long long b) {
    asm("fma.rn.f32x2 %0, %1, %2, %0;" : "+l"(d) : "l"(a), "l"(b));
}
__device__ __forceinline__ unsigned long long packf2(float lo, float hi) {
    unsigned long long p;
    asm("mov.b64 %0, {%1, %2};" : "=l"(p) : "f"(lo), "f"(hi));
    return p;
}
__device__ __forceinline__ uint32_t encf(float f) {
    uint32_t u = __float_as_uint(f);
    return (u & 0x80000000u) ? ~u : (u | 0x80000000u);
}
__device__ __forceinline__ float decf(uint32_t e) {
    uint32_t u = (e & 0x80000000u) ? (e & 0x7fffffffu) : ~e;
    return __uint_as_float(u);
}
__device__ __forceinline__ uint32_t packh2(__half a, __half b) {
    __half2 h = __halves2half2(a, b);
    return *reinterpret_cast<uint32_t*>(&h);
}

// ===== launch #1: fused init + prep A + prep B (+ pair-transposed codebook) =====
__global__ void prep_kernel(const float* __restrict__ x, const float* __restrict__ cb) {
    int b = blockIdx.x;
    int gt = b * 256 + threadIdx.x;

    if (gt < RTOT) {                 // init arrays (first 128 blocks)
        g_best[gt] = ~0ull;
        g_best2[gt] = 0xFFFFFFFFu;
        g_isfix[gt] = 0;
        g_fbest[gt] = ~0ull;
        if (gt == 0) g_fixcnt = 0;
    }

    if (b < 4096) {
        int t = gt;                  // A: rows 0..32767, 32 threads/row
        int row = t >> 5, u = t & 31;
        int ks = u >> 1, kh = u & 1;
        const float* r = x + (size_t)row * CDIM + ks * 16 + kh * 8;
        float s = 0.f;
        __half h[8];
#pragma unroll
        for (int i = 0; i < 8; ++i) { float v = r[i]; s = fmaf(v, v, s); h[i] = __float2half(v); }
        uint4 val;
        val.x = packh2(h[0], h[1]); val.y = packh2(h[2], h[3]);
        val.z = packh2(h[4], h[5]); val.w = packh2(h[6], h[7]);
        int tile = row >> 7, rl = row & 127;
        int phys = (rl * 2 + kh) ^ ((rl >> 2) & 1);
        g_Aimg[(size_t)tile * 4096 + ks * 256 + phys] = val;
#pragma unroll
        for (int o = 16; o; o >>= 1) s += __shfl_xor_sync(0xffffffffu, s, o);
        if ((t & 31) == 0) g_xsq[row] = s;
    } else {
        int t = gt - 4096 * 256;     // B: rows 0..8191
        int row = t >> 5, u = t & 31;
        int ks = u >> 1, kh = u & 1;
        int kext = ks * 16 + kh * 8;
        const float* r = cb + (size_t)row * CDIM + kext;
        float s = 0.f;
        __half h[8];
#pragma unroll
        for (int i = 0; i < 8; ++i) { float v = r[i]; s = fmaf(v, v, s); h[i] = __float2half(v); }
        uint4 val;
        val.x = packh2(h[0], h[1]); val.y = packh2(h[2], h[3]);
        val.z = packh2(h[4], h[5]); val.w = packh2(h[6], h[7]);
        int nt = row >> 6, rl = row & 63;
        int phys = (rl * 2 + kh) ^ ((rl >> 2) & 1);
        g_Bimg[(size_t)nt * 2048 + ks * 128 + phys] = val;
        // pair-transposed codebook: cbPu[q2][code]
        int q2b = kext >> 1;
#pragma unroll
        for (int i = 0; i < 4; ++i)
            g_cbPu[(size_t)(q2b + i) * KTOT + row] = packf2(r[2 * i], r[2 * i + 1]);
#pragma unroll
        for (int o = 16; o; o >>= 1) s += __shfl_xor_sync(0xffffffffu, s, o);
        if ((t & 31) == 0) { g_cbsq[row] = s; g_cbsqo[row] = s + VOFF; }
    }
}

// ===== launch #2: main HMMA kernel — partial A-stationary, 512 threads =====
__device__ __forceinline__ void issue_A(uint32_t smemA, int m, int tid) {
    const uint4* src = g_Aimg + (size_t)m * 4096 + tid;
#pragma unroll
    for (int i = 0; i < 8; ++i)
        cp_async16(smemA + (tid + i * 512) * 16, src + i * 512);
}
__device__ __forceinline__ void produce_stage(uint32_t smB, uint32_t bar, int jpi, int j, int tid) {
    int sp = jpi & 3;
    int par = (((jpi >> 2) & 1) ^ 1);
    MBAR_WAIT(bar + 32 + sp * 8, par);             // empty[sp]
    const uint4* src = g_Bimg + (size_t)(j & (NUM_NT - 1)) * 2048 + tid;
    uint32_t dst = smB + sp * 32768 + tid * 16;
#pragma unroll
    for (int i = 0; i < 4; ++i)
        cp_async16(dst + i * 8192, src + i * 512);
    CP_ASYNC_MBAR_ARRIVE(bar + sp * 8);            // full[sp]
}

__global__ __launch_bounds__(THREADS, 1)
void vq_hmma_kernel() {
    extern __shared__ char smem[];
    uint32_t sb = smem_u32(smem);
    uint32_t smA = sb + SMEM_A;
    uint32_t smB = sb + SMEM_B;
    uint32_t bar = sb + SMEM_BAR;

    int tid = threadIdx.x;
    int l = tid & 31, w = tid >> 5;
    int wm = w >> 1, wn = w & 1;     // wm: 8 row-slices of 16; wn: 2 col-halves of 32

    uint32_t aoff, boff[2];
    {
        int row = wm * 16 + (l & 15);
        int kh = l >> 4;
        aoff = (uint32_t)(((row * 2 + kh) ^ ((row >> 2) & 1)) << 4);
    }
#pragma unroll
    for (int g = 0; g < 2; ++g) {
        int code = wn * 32 + g * 16 + (l & 7) + ((l >> 4) << 3);
        int kh = (l >> 3) & 1;
        boff[g] = (uint32_t)(((code * 2 + kh) ^ ((code >> 2) & 1)) << 4);
    }

    int start = (int)(((long long)blockIdx.x * JOBS) / NCTA);
    int end   = (int)(((long long)(blockIdx.x + 1) * JOBS) / NCTA);
    int njobs = end - start;

    if (tid == 0) {
#pragma unroll
        for (int s = 0; s < 4; ++s) {
            MBARRIER_INIT(bar + s * 8, 512);        // full
            MBARRIER_INIT(bar + 32 + s * 8, 512);   // empty
        }
    }
    __syncthreads();

    int cur_m = start >> 7;
    issue_A(smA, cur_m, tid); CP_COMMIT();
#pragma unroll
    for (int p = 0; p < 3; ++p)
        if (p < njobs) produce_stage(smB, bar, p, start + p, tid);
    CP_WAIT(0);
    __syncthreads();

    // ---- partial A-stationary: first 8 ksteps in regs (32 regs, no spill) ----
    uint32_t areg[ASTAT][4];
#pragma unroll
    for (int ks = 0; ks < ASTAT; ++ks)
        ldsm4(areg[ks], smA + ks * 4096 + aoff);

    float rb[2] = {3.4e38f, 3.4e38f};
    float rs[2] = {3.4e38f, 3.4e38f};
    int   ri[2] = {0, 0};

    for (int ji = 0; ji < njobs; ++ji) {
        int j = start + ji;
        int ntj = j & (NUM_NT - 1);
        int s = ji & 3;

        MBAR_WAIT(bar + s * 8, (ji >> 2) & 1);      // full[s]

        float qv[8];
        int qbase = ntj * NT + wn * 32 + (l & 3) * 2;
#pragma unroll
        for (int nb = 0; nb < 4; ++nb) {
            qv[nb * 2]     = __ldg(&g_cbsqo[qbase + nb * 8]);
            qv[nb * 2 + 1] = __ldg(&g_cbsqo[qbase + nb * 8 + 1]);
        }

        float acc[4][4];
#pragma unroll
        for (int nb = 0; nb < 4; ++nb)
#pragma unroll
            for (int q = 0; q < 4; ++q) acc[nb][q] = 0.f;

        uint32_t Bstage = smB + s * 32768;
#pragma unroll
        for (int ks = 0; ks < KSTEPS; ++ks) {
            uint32_t Bpan = Bstage + ks * 2048;
            uint32_t bf[2][4];
            ldsm4(bf[0], Bpan + boff[0]);
            ldsm4(bf[1], Bpan + boff[1]);
            uint32_t af[4];
            const uint32_t* ap;
            if (ks < ASTAT) {
                ap = areg[ks];
            } else {
                ldsm4(af, smA + ks * 4096 + aoff);
                ap = af;
            }
#pragma unroll
            for (int g = 0; g < 2; ++g) {
                mma16816(acc[g*2  ], ap, bf[g][0], bf[g][1]);
                mma16816(acc[g*2+1], ap, bf[g][2], bf[g][3]);
            }
        }

        MBARRIER_ARRIVE(bar + 32 + s * 8);          // empty[s]

        // epilogue (registers only)
#pragma unroll
        for (int h = 0; h < 2; ++h) {
            uint32_t k1 = 0xFFFFFFFFu, k2 = 0xFFFFFFFFu;
#pragma unroll
            for (int nb = 0; nb < 4; ++nb)
#pragma unroll
                for (int c = 0; c < 2; ++c) {
                    float v = fmaf(-2.f, acc[nb][h * 2 + c], qv[nb * 2 + c]);
                    uint32_t k = (__float_as_uint(v) & 0xFFFFFFF8u) | (uint32_t)(nb * 2 + c);
                    uint32_t t = max(k1, k);
                    k1 = min(k1, k);
                    k2 = min(k2, t);
                }
            float v1 = __uint_as_float(k1 & 0xFFFFFFF8u);
            float v2 = __uint_as_float(k2 & 0xFFFFFFF8u);
            int li = (int)(k1 & 7u);
            int gidx = qbase + (li >> 1) * 8 + (li & 1);
            if (v1 < rb[h]) {
                rs[h] = fminf(rb[h], v2);
                rb[h] = v1; ri[h] = gidx;
            } else {
                rs[h] = fminf(rs[h], v1);
            }
        }

        int jn = j + 1;
        bool m_change = (jn < end) && ((jn >> 7) != cur_m);
        if (m_change || jn == end) {
#pragma unroll
            for (int h = 0; h < 2; ++h) {
                float bv = rb[h], sv = rs[h];
                int bi = ri[h];
#pragma unroll
                for (int o = 1; o < 4; o <<= 1) {
                    float ov = __shfl_xor_sync(0xffffffffu, bv, o);
                    int   oi = __shfl_xor_sync(0xffffffffu, bi, o);
                    float os = __shfl_xor_sync(0xffffffffu, sv, o);
                    if (ov < bv || (ov == bv && oi < bi)) {
                        sv = fminf(bv, os); bv = ov; bi = oi;
                    } else {
                        sv = fminf(sv, ov);
                    }
                }
                if ((l & 3) == 0) {
                    int r = cur_m * MT + wm * 16 + h * 8 + (l >> 2);
                    unsigned long long key =
                        ((unsigned long long)encf(bv) << 32) | (uint32_t)bi;
                    unsigned long long old = atomicMin(&g_best[r], key);
                    uint32_t oldenc = (uint32_t)(old >> 32);
                    uint32_t be = encf(bv);
                    uint32_t cand = min(encf(sv), max(be, oldenc));
                    atomicMin(&g_best2[r], cand);
                }
                rb[h] = 3.4e38f; rs[h] = 3.4e38f; ri[h] = 0;
            }
        }

        if (ji + 3 < njobs) produce_stage(smB, bar, ji + 3, start + ji + 3, tid);

        if (m_change) {
            cur_m = jn >> 7;
            __syncthreads();                        // all warps done reading smA
            issue_A(smA, cur_m, tid); CP_COMMIT();
            CP_WAIT(0);
            __syncthreads();                        // new A visible
#pragma unroll
            for (int ks = 0; ks < ASTAT; ++ks)      // refill stationary A regs
                ldsm4(areg[ks], smA + ks * 4096 + aoff);
        }
    }
}

// ===== launch #3: finalize, flag close rows =====
__global__ void final_kernel(float* __restrict__ out) {
    int i = blockIdx.x * 256 + threadIdx.x;
    unsigned long long key = g_best[i];
    int idx = (int)(uint32_t)key;
    float val = decf((uint32_t)(key >> 32)) - VOFF;
    float sec = decf(g_best2[i]) - VOFF;
    out[IDX_OFF + i]  = (float)idx;
    out[DIST_OFF + i] = g_xsq[i] + val;
    g_idx[i] = idx;
    if (sec - val < MARGIN) {
        g_isfix[i] = 1;
        int p = atomicAdd(&g_fixcnt, 1);
        g_fixrows[p] = i;
    }
}

// ===== launch #4: exact fp32 rescan v2 — coalesced via pair-transposed codebook =====
// 32 rows/group; warp owns 4 rows; lane owns 4 consecutive codes; 16 FFMA2/q2.
__global__ __launch_bounds__(256) void fixup_kernel(const float* __restrict__ x) {
    __shared__ float xs[FIXROWS][CDIM];
    int tid = threadIdx.x;
    int n = g_fixcnt;
    int ngroups = (n + FIXROWS - 1) / FIXROWS;
    int slice = blockIdx.x & (KSLICES - 1);     // 512-code slice
    int g0 = blockIdx.x >> 4;
    int w = tid >> 5, l = tid & 31;
    for (int g = g0; g < ngroups; g += NCTA) {
        __syncthreads();
        for (int i = tid; i < FIXROWS * 64; i += 256) {
            int r = i >> 6, q4 = i & 63;
            int fr = g * FIXROWS + r;
            int row = g_fixrows[(fr < n) ? fr : g * FIXROWS];
            *reinterpret_cast<float4*>(&xs[r][q4 * 4]) =
                reinterpret_cast<const float4*>(x)[(size_t)row * 64 + q4];
        }
        __syncthreads();

        unsigned long long bk[4] = {~0ull, ~0ull, ~0ull, ~0ull};
#pragma unroll 1
        for (int chunk = 0; chunk < 4; ++chunk) {
            int c0 = slice * 512 + chunk * 128 + l * 4;
            unsigned long long acc2[4][4];
#pragma unroll
            for (int r = 0; r < 4; ++r)
#pragma unroll
                for (int jc = 0; jc < 4; ++jc) acc2[r][jc] = 0ull;
#pragma unroll 4
            for (int q2 = 0; q2 < 128; ++q2) {
                ulonglong2 cbA = *reinterpret_cast<const ulonglong2*>(
                    &g_cbPu[(size_t)q2 * KTOT + c0]);
                ulonglong2 cbB = *reinterpret_cast<const ulonglong2*>(
                    &g_cbPu[(size_t)q2 * KTOT + c0 + 2]);
#pragma unroll
                for (int r = 0; r < 4; ++r) {
                    unsigned long long xp =
                        *reinterpret_cast<const unsigned long long*>(&xs[w * 4 + r][q2 * 2]);
                    ffma2(acc2[r][0], xp, cbA.x);
                    ffma2(acc2[r][1], xp, cbA.y);
                    ffma2(acc2[r][2], xp, cbB.x);
                    ffma2(acc2[r][3], xp, cbB.y);
                }
            }
#pragma unroll
            for (int jc = 0; jc < 4; ++jc) {
                float cq = __ldg(&g_cbsq[c0 + jc]);
#pragma unroll
                for (int r = 0; r < 4; ++r) {
                    float lo, hi;
                    asm("mov.b64 {%0,%1}, %2;" : "=f"(lo), "=f"(hi) : "l"(acc2[r][jc]));
                    float val = fmaf(-2.f, lo + hi, cq);
                    unsigned long long key =
                        ((unsigned long long)encf(val) << 32) | (uint32_t)(c0 + jc);
                    bk[r] = min(bk[r], key);
                }
            }
        }
        // warp reduce packed keys (exact first-index ties)
#pragma unroll
        for (int r = 0; r < 4; ++r) {
#pragma unroll
            for (int o = 16; o; o >>= 1) {
                unsigned long long ok = __shfl_xor_sync(0xffffffffu, bk[r], o);
                bk[r] = min(bk[r], ok);
            }
        }
        if (l == 0) {
#pragma unroll
            for (int r = 0; r < 4; ++r) {
                int fr = g * FIXROWS + w * 4 + r;
                if (fr < n) atomicMin(&g_fbest[g_fixrows[fr]], bk[r]);
            }
        }
    }
}

// ===== launch #5: apply fixups + gather codes =====
__global__ void gather_kernel(const float* __restrict__ cb, float* __restrict__ out) {
    __shared__ int s_idx[4];
    int tid = threadIdx.x;
    int rslot = tid >> 6;
    int row = blockIdx.x * 4 + rslot;
    int c = tid & 63;
    if (c == 0) {
        int idx;
        if (g_isfix[row]) {
            unsigned long long best = g_fbest[row];
            idx = (int)(uint32_t)best;
            out[IDX_OFF + row]  = (float)idx;
            out[DIST_OFF + row] = g_xsq[row] + decf((uint32_t)(best >> 32));
        } else {
            idx = g_idx[row];
        }
        s_idx[rslot] = idx;
    }
    __syncthreads();
    int idx = s_idx[rslot];
    reinterpret_cast<float4*>(out)[(size_t)row * 64 + c] =
        reinterpret_cast<const float4*>(cb)[(size_t)idx * 64 + c];
}

extern "C" void kernel_launch(void* const* d_in, const int* in_sizes, int n_in,
                              void* d_out, int out_size) {
    const float* x  = (const float*)d_in[0];   // z_e_x  [8,4096,256] f32
    const float* cb = (const float*)d_in[1];   // codebook [8192,256] f32
    float* out = (float*)d_out;                // codes | idx | distances (f32)

    cudaFuncSetAttribute(vq_hmma_kernel,
                         cudaFuncAttributeMaxDynamicSharedMemorySize, SMEM_TOTAL);

    prep_kernel<<<5120, 256>>>(x, cb);                     // #1 (init + prep A/B + cbP)
    vq_hmma_kernel<<<NCTA, THREADS, SMEM_TOTAL>>>();       // #2
    final_kernel<<<RTOT / 256, 256>>>(out);                // #3
    fixup_kernel<<<NCTA * KSLICES, 256>>>(x);              // #4  <- ncu capture slot
    gather_kernel<<<RTOT / 4, 256>>>(cb, out);             // #5
}